// round 3
// baseline (speedup 1.0000x reference)
#include <cuda_runtime.h>
#include <math.h>

// ---------------------------------------------------------------- constants
#define Bb   4
#define Tt   2048
#define Hh   1024
#define NHh  16
#define HDh  64
#define BT   (Bb*Tt)          // 8192 tokens
#define BTH  (BT*Hh)          // 8388608
#define DECAYC (-0.6065306597126334f)
#define GN_EPS (HDh*1e-5f)    // 6.4e-4

// ---------------------------------------------------------------- scratch (aliased by liveness)
// xr..xg live: prep6 -> gemms/LoRA-s1. Reused as head-layout scan operands after.
__device__ float g_xr[BTH], g_xw[BTH], g_xk[BTH], g_xv[BTH], g_xa[BTH], g_xg[BTH];
__device__ float g_r[BTH], g_k[BTH], g_v0[BTH];
__device__ float g_hw[BT*64], g_hv[BT*64], g_ha[BT*64], g_hg[BT*160];
__device__ float g_wl[BTH], g_vl[BTH], g_al[BTH], g_gl[BTH];

// aliases: head-layout operands live only after their source x-buffer is dead
#define g_rH  g_xr
#define g_wHe g_xw
#define g_kH  g_xk
#define g_vH  g_xv
#define g_aH  g_xa
#define g_bH  g_xg
#define g_oH  g_wl   // wl consumed by prep_scan before scan writes oH
#define g_y   g_vl   // vl consumed by prep_scan before out_stage writes y

// ---------------------------------------------------------------- helpers
__device__ __forceinline__ float warp_sum(float v) {
    #pragma unroll
    for (int o = 16; o > 0; o >>= 1) v += __shfl_xor_sync(0xffffffffu, v, o);
    return v;
}

// ---------------------------------------------------------------- kernel 1: token-shift mixes
__global__ void prep6_kernel(const float* __restrict__ x,
                             const float* __restrict__ mr, const float* __restrict__ mw,
                             const float* __restrict__ mk, const float* __restrict__ mv,
                             const float* __restrict__ ma, const float* __restrict__ mg) {
    int idx = blockIdx.x * blockDim.x + threadIdx.x;
    if (idx >= BTH) return;
    int ch = idx & (Hh - 1);
    int tok = idx >> 10;          // token index within (B*T)
    int t = tok & (Tt - 1);
    float xc = x[idx];
    float xp = (t == 0) ? 0.f : x[idx - Hh];
    float d = xp - xc;
    g_xr[idx] = xc + d * mr[ch];
    g_xw[idx] = xc + d * mw[ch];
    g_xk[idx] = xc + d * mk[ch];
    g_xv[idx] = xc + d * mv[ch];
    g_xa[idx] = xc + d * ma[ch];
    g_xg[idx] = xc + d * mg[ch];
}

// ---------------------------------------------------------------- GEMM (big): 128x128x8 tiles, no guards
// requires M%128==0, N%128==0, K%8==0. act: 0 none, 1 tanh, 2 sigmoid
__global__ __launch_bounds__(256, 2)
void gemm_big(const float* __restrict__ A, const float* __restrict__ Bm,
              float* __restrict__ C, int M, int N, int K,
              const float* __restrict__ bias, int act) {
    __shared__ float As[8][128];
    __shared__ float Bs[8][128];
    int tid = threadIdx.x;
    int row0 = blockIdx.y * 128;
    int col0 = blockIdx.x * 128;
    int arow = tid >> 1, ac4 = (tid & 1) * 4;
    int brow = tid >> 5, bc4 = (tid & 31) * 4;
    int ty = tid >> 4, tx = tid & 15;
    int mb = ty * 8, nb = tx * 8;
    float acc[8][8];
    #pragma unroll
    for (int i = 0; i < 8; i++)
        #pragma unroll
        for (int j = 0; j < 8; j++) acc[i][j] = 0.f;

    const float* Aptr = A + (size_t)(row0 + arow) * K + ac4;
    const float* Bptr = Bm + (size_t)brow * N + col0 + bc4;

    for (int k0 = 0; k0 < K; k0 += 8) {
        float4 av = *(const float4*)(Aptr + k0);
        As[ac4 + 0][arow] = av.x;
        As[ac4 + 1][arow] = av.y;
        As[ac4 + 2][arow] = av.z;
        As[ac4 + 3][arow] = av.w;
        float4 bv = *(const float4*)(Bptr + (size_t)k0 * N);
        *(float4*)&Bs[brow][bc4] = bv;
        __syncthreads();
        #pragma unroll
        for (int kk = 0; kk < 8; kk++) {
            float a[8], b[8];
            *(float4*)&a[0] = *(const float4*)&As[kk][mb];
            *(float4*)&a[4] = *(const float4*)&As[kk][mb + 4];
            *(float4*)&b[0] = *(const float4*)&Bs[kk][nb];
            *(float4*)&b[4] = *(const float4*)&Bs[kk][nb + 4];
            #pragma unroll
            for (int i = 0; i < 8; i++)
                #pragma unroll
                for (int j = 0; j < 8; j++) acc[i][j] += a[i] * b[j];
        }
        __syncthreads();
    }
    #pragma unroll
    for (int i = 0; i < 8; i++) {
        int r = row0 + mb + i;
        #pragma unroll
        for (int j = 0; j < 8; j++) {
            int c = col0 + nb + j;
            float v = acc[i][j];
            if (bias) v += bias[c];
            if (act == 1) v = tanhf(v);
            else if (act == 2) v = 1.f / (1.f + expf(-v));
            C[(size_t)r * N + c] = v;
        }
    }
}

// ---------------------------------------------------------------- GEMM (small N): 64x64x8, col-guarded
// requires M%64==0, K%8==0. N arbitrary.
__global__ __launch_bounds__(128)
void gemm_small(const float* __restrict__ A, const float* __restrict__ Bm,
                float* __restrict__ C, int M, int N, int K,
                const float* __restrict__ bias, int act) {
    __shared__ float As[8][64];
    __shared__ float Bs[8][64];
    int tid = threadIdx.x;
    int row0 = blockIdx.y * 64;
    int col0 = blockIdx.x * 64;
    int arow = tid >> 1, ac4 = (tid & 1) * 4;
    int brow = tid >> 4, bc4 = (tid & 15) * 4;
    int ty = tid >> 4, tx = tid & 15;
    int mb = ty * 8, nb = tx * 4;
    float acc[8][4];
    #pragma unroll
    for (int i = 0; i < 8; i++)
        #pragma unroll
        for (int j = 0; j < 4; j++) acc[i][j] = 0.f;

    for (int k0 = 0; k0 < K; k0 += 8) {
        float4 av = *(const float4*)&A[(size_t)(row0 + arow) * K + k0 + ac4];
        As[ac4 + 0][arow] = av.x;
        As[ac4 + 1][arow] = av.y;
        As[ac4 + 2][arow] = av.z;
        As[ac4 + 3][arow] = av.w;
        #pragma unroll
        for (int ii = 0; ii < 4; ii++) {
            int cc = col0 + bc4 + ii;
            Bs[brow][bc4 + ii] = (cc < N) ? Bm[(size_t)(k0 + brow) * N + cc] : 0.f;
        }
        __syncthreads();
        #pragma unroll
        for (int kk = 0; kk < 8; kk++) {
            float a[8], b[4];
            *(float4*)&a[0] = *(const float4*)&As[kk][mb];
            *(float4*)&a[4] = *(const float4*)&As[kk][mb + 4];
            *(float4*)&b[0] = *(const float4*)&Bs[kk][nb];
            #pragma unroll
            for (int i = 0; i < 8; i++)
                #pragma unroll
                for (int j = 0; j < 4; j++) acc[i][j] += a[i] * b[j];
        }
        __syncthreads();
    }
    #pragma unroll
    for (int i = 0; i < 8; i++) {
        int r = row0 + mb + i;
        #pragma unroll
        for (int j = 0; j < 4; j++) {
            int c = col0 + nb + j;
            if (c >= N) continue;
            float v = acc[i][j];
            if (bias) v += bias[c];
            if (act == 1) v = tanhf(v);
            else if (act == 2) v = 1.f / (1.f + expf(-v));
            C[(size_t)r * N + c] = v;
        }
    }
}

// ---------------------------------------------------------------- kernel: per-(token,head) prep for scan
// blocks = BT*NH, 32 threads each (2 channels per thread)
// reads g_k,g_al,g_r,g_wl,g_v0,g_vl ; writes head-layout aliases (x-bufs, all dead)
__global__ void prep_scan_kernel(const float* __restrict__ v_first,
                                 const float* __restrict__ k_k,
                                 const float* __restrict__ k_a) {
    int bh = blockIdx.x;
    int tok = bh >> 4;            // token (b*T + t)
    int h = bh & 15;
    int b = tok >> 11;
    int t = tok & (Tt - 1);
    int lane = threadIdx.x;
    int ofs = tok * Hh + h * 64;
    int hofs = (((b * NHh + h) * Tt) + t) * 64;
    int hd0 = h * 64 + lane, hd1 = hd0 + 32;

    float kv0 = g_k[ofs + lane],      kv1 = g_k[ofs + lane + 32];
    float av0 = g_al[ofs + lane],     av1 = g_al[ofs + lane + 32];
    float kk0 = kv0 * k_k[hd0],       kk1 = kv1 * k_k[hd1];
    float ss = warp_sum(kk0 * kk0 + kk1 * kk1);
    float inv = 1.f / fmaxf(sqrtf(ss), 1e-12f);

    // read all x-sourced values BEFORE writing aliases (same indices only, but be explicit)
    float r0 = g_r[ofs + lane],  r1 = g_r[ofs + lane + 32];
    float w0 = g_wl[ofs + lane], w1 = g_wl[ofs + lane + 32];
    float vv0 = g_v0[ofs + lane], vv1 = g_v0[ofs + lane + 32];
    float vl0 = g_vl[ofs + lane], vl1 = g_vl[ofs + lane + 32];
    float vf0 = v_first[ofs + lane], vf1 = v_first[ofs + lane + 32];

    #pragma unroll
    for (int e = 0; e < 2; e++) {
        int d = lane + e * 32;
        float kv = e ? kv1 : kv0;
        float aa = e ? av1 : av0;
        float kkn = (e ? kk1 : kk0) * inv;
        g_aH[hofs + d] = -kkn;
        g_bH[hofs + d] = kkn * aa;
        g_kH[hofs + d] = kv * (1.f + (aa - 1.f) * k_a[h * 64 + d]);
        g_rH[hofs + d] = e ? r1 : r0;
        g_wHe[hofs + d] = __expf(DECAYC * (e ? w1 : w0));   // wl already sigmoid'd
        float v0v = e ? vv1 : vv0;
        g_vH[hofs + d] = v0v + (e ? vl1 : vl0) * ((e ? vf1 : vf0) - v0v);
    }
}

// ---------------------------------------------------------------- kernel: sequential WKV7 scan
// 128 blocks (head, half), 128 threads: v-row (32) x k-chunk (4 of 16)
__global__ __launch_bounds__(128)
void scan_kernel() {
    int head = blockIdx.x >> 1;      // b*NH + h
    int half = blockIdx.x & 1;
    size_t base = (size_t)head * Tt * 64;
    int tid = threadIdx.x;
    int v = (tid >> 2) + half * 32;  // 0..63
    int c = tid & 3;
    int co = c * 16;

    __shared__ float sbuf[2][6 * 64];

    const float* srcs[6] = { g_rH + base, g_wHe + base, g_kH + base,
                             g_vH + base, g_aH + base, g_bH + base };
    int e0 = tid, e1 = tid + 128, e2 = tid + 256;
    const float* p0 = srcs[e0 >> 6] + (e0 & 63);
    const float* p1 = srcs[e1 >> 6] + (e1 & 63);
    const float* p2 = srcs[e2 >> 6] + (e2 & 63);

    sbuf[0][e0] = *p0; sbuf[0][e1] = *p1; sbuf[0][e2] = *p2;
    p0 += 64; p1 += 64; p2 += 64;
    __syncthreads();

    float S[16];
    #pragma unroll
    for (int j = 0; j < 16; j++) S[j] = 0.f;

    float* outp = g_oH + base + v;

    for (int t = 0; t < Tt; t++) {
        float* nx = sbuf[(t + 1) & 1];
        if (t + 1 < Tt) {
            nx[e0] = *p0; nx[e1] = *p1; nx[e2] = *p2;
            p0 += 64; p1 += 64; p2 += 64;
        }
        const float* cu = sbuf[t & 1];
        const float* rs = cu;
        const float* ws = cu + 64;
        const float* ks = cu + 128;
        const float* vs = cu + 192;
        const float* as_ = cu + 256;
        const float* bs = cu + 320;

        float sa = 0.f;
        #pragma unroll
        for (int j = 0; j < 16; j++) sa += S[j] * as_[co + j];
        sa += __shfl_xor_sync(0xffffffffu, sa, 1);
        sa += __shfl_xor_sync(0xffffffffu, sa, 2);

        float vt = vs[v];
        float o = 0.f;
        #pragma unroll
        for (int j = 0; j < 16; j++) {
            float s = S[j] * ws[co + j] + sa * bs[co + j] + vt * ks[co + j];
            S[j] = s;
            o += s * rs[co + j];
        }
        o += __shfl_xor_sync(0xffffffffu, o, 1);
        o += __shfl_xor_sync(0xffffffffu, o, 2);
        if (c == 0) outp[(size_t)t * 64] = o;
        __syncthreads();
    }
}

// ---------------------------------------------------------------- kernel: groupnorm + correction + gate
__global__ void out_stage_kernel(const float* __restrict__ r_k,
                                 const float* __restrict__ gn_w,
                                 const float* __restrict__ gn_b) {
    int bh = blockIdx.x;
    int tok = bh >> 4;
    int h = bh & 15;
    int b = tok >> 11;
    int t = tok & (Tt - 1);
    int lane = threadIdx.x;
    int ofs = tok * Hh + h * 64;
    int hofs = (((b * NHh + h) * Tt) + t) * 64;

    float o0 = g_oH[hofs + lane],      o1 = g_oH[hofs + lane + 32];
    float r0 = g_rH[hofs + lane],      r1 = g_rH[hofs + lane + 32];
    float k0 = g_kH[hofs + lane],      k1 = g_kH[hofs + lane + 32];
    float v0 = g_vH[hofs + lane],      v1 = g_vH[hofs + lane + 32];

    float mu = warp_sum(o0 + o1) * (1.f / 64.f);
    float sq = warp_sum(o0 * o0 + o1 * o1) * (1.f / 64.f);
    float var = sq - mu * mu;
    float rstd = rsqrtf(var + GN_EPS);
    float dot = warp_sum(r0 * k0 * r_k[h * 64 + lane] + r1 * k1 * r_k[h * 64 + lane + 32]);

    #pragma unroll
    for (int e = 0; e < 2; e++) {
        int d = lane + e * 32;
        float oo = e ? o1 : o0;
        float vv = e ? v1 : v0;
        float on = (oo - mu) * rstd * gn_w[h * 64 + d] + gn_b[h * 64 + d];
        g_y[ofs + d] = (on + dot * vv) * g_gl[ofs + d];
    }
}

// ---------------------------------------------------------------- launch
extern "C" void kernel_launch(void* const* d_in, const int* in_sizes, int n_in,
                              void* d_out, int out_size) {
    const float* x       = (const float*)d_in[0];
    const float* v_first = (const float*)d_in[1];
    const float* x_r = (const float*)d_in[2];
    const float* x_w = (const float*)d_in[3];
    const float* x_k = (const float*)d_in[4];
    const float* x_v = (const float*)d_in[5];
    const float* x_a = (const float*)d_in[6];
    const float* x_g = (const float*)d_in[7];
    const float* k_k = (const float*)d_in[8];
    const float* k_a = (const float*)d_in[9];
    const float* r_k = (const float*)d_in[10];
    const float* W_r = (const float*)d_in[11];
    const float* W_k = (const float*)d_in[12];
    const float* W_v = (const float*)d_in[13];
    const float* W_o = (const float*)d_in[14];
    const float* wA  = (const float*)d_in[15];
    const float* wB  = (const float*)d_in[16];
    const float* wb  = (const float*)d_in[17];
    const float* vA  = (const float*)d_in[18];
    const float* vB  = (const float*)d_in[19];
    const float* vb  = (const float*)d_in[20];
    const float* aA  = (const float*)d_in[21];
    const float* aB  = (const float*)d_in[22];
    const float* ab  = (const float*)d_in[23];
    const float* gA  = (const float*)d_in[24];
    const float* gB  = (const float*)d_in[25];
    const float* gn_w = (const float*)d_in[26];
    const float* gn_b = (const float*)d_in[27];
    float* out = (float*)d_out;

    float *p_xr, *p_xw, *p_xk, *p_xv, *p_xa, *p_xg;
    float *p_r, *p_k, *p_v0, *p_hw, *p_hv, *p_ha, *p_hg;
    float *p_wl, *p_vl, *p_al, *p_gl;
    cudaGetSymbolAddress((void**)&p_xr, g_xr);
    cudaGetSymbolAddress((void**)&p_xw, g_xw);
    cudaGetSymbolAddress((void**)&p_xk, g_xk);
    cudaGetSymbolAddress((void**)&p_xv, g_xv);
    cudaGetSymbolAddress((void**)&p_xa, g_xa);
    cudaGetSymbolAddress((void**)&p_xg, g_xg);
    cudaGetSymbolAddress((void**)&p_r,  g_r);
    cudaGetSymbolAddress((void**)&p_k,  g_k);
    cudaGetSymbolAddress((void**)&p_v0, g_v0);
    cudaGetSymbolAddress((void**)&p_hw, g_hw);
    cudaGetSymbolAddress((void**)&p_hv, g_hv);
    cudaGetSymbolAddress((void**)&p_ha, g_ha);
    cudaGetSymbolAddress((void**)&p_hg, g_hg);
    cudaGetSymbolAddress((void**)&p_wl, g_wl);
    cudaGetSymbolAddress((void**)&p_vl, g_vl);
    cudaGetSymbolAddress((void**)&p_al, g_al);
    cudaGetSymbolAddress((void**)&p_gl, g_gl);

    // 1) token-shift mixes
    prep6_kernel<<<(BTH + 255) / 256, 256>>>(x, x_r, x_w, x_k, x_v, x_a, x_g);

    // 2) big projections: r, k, v0
    dim3 gb(Hh / 128, BT / 128);
    gemm_big<<<gb, 256>>>(p_xr, W_r, p_r,  BT, Hh, Hh, nullptr, 0);
    gemm_big<<<gb, 256>>>(p_xk, W_k, p_k,  BT, Hh, Hh, nullptr, 0);
    gemm_big<<<gb, 256>>>(p_xv, W_v, p_v0, BT, Hh, Hh, nullptr, 0);

    // 3) LoRA stage 1 (skinny N)
    dim3 gs64(1, BT / 64);
    dim3 gs160(3, BT / 64);
    gemm_small<<<gs64, 128>>>(p_xw, wA, p_hw, BT, 64, Hh, nullptr, 1);   // tanh
    gemm_small<<<gs64, 128>>>(p_xv, vA, p_hv, BT, 64, Hh, nullptr, 0);
    gemm_small<<<gs64, 128>>>(p_xa, aA, p_ha, BT, 64, Hh, nullptr, 0);
    gemm_small<<<gs160, 128>>>(p_xg, gA, p_hg, BT, 160, Hh, nullptr, 2); // sigmoid

    // 4) LoRA stage 2 (N=1024)
    gemm_big<<<gb, 256>>>(p_hw, wB, p_wl, BT, Hh, 64,  wb, 2);           // sigmoid(.+wb)
    gemm_big<<<gb, 256>>>(p_hv, vB, p_vl, BT, Hh, 64,  vb, 2);
    gemm_big<<<gb, 256>>>(p_ha, aB, p_al, BT, Hh, 64,  ab, 2);
    gemm_big<<<gb, 256>>>(p_hg, gB, p_gl, BT, Hh, 160, nullptr, 0);

    // 5) per-token/head prep into head layout (x-bufs now dead -> reused)
    prep_scan_kernel<<<BT * NHh, 32>>>(v_first, k_k, k_a);

    // 6) sequential scan (writes oH = g_wl, dead)
    scan_kernel<<<Bb * NHh * 2, 128>>>();

    // 7) groupnorm + correction + gate (writes y = g_vl, dead)
    out_stage_kernel<<<BT * NHh, 32>>>(r_k, gn_w, gn_b);

    // 8) output projection
    float *p_y;
    cudaGetSymbolAddress((void**)&p_y, g_vl);
    gemm_big<<<gb, 256>>>(p_y, W_o, out, BT, Hh, Hh, nullptr, 0);

    (void)in_sizes; (void)n_in; (void)out_size;
}

// round 5
// speedup vs baseline: 1.3482x; 1.3482x over previous
#include <cuda_runtime.h>
#include <cuda_bf16.h>
#include <math.h>
#include <stdint.h>

// ---------------------------------------------------------------- constants
#define Bb   4
#define Tt   2048
#define Hh   1024
#define NHh  16
#define HDh  64
#define BT   (Bb*Tt)          // 8192 tokens
#define BTH  (BT*Hh)          // 8388608
#define DECAYC (-0.6065306597126334f)
#define GN_EPS (HDh*1e-5f)    // 6.4e-4

// ---------------------------------------------------------------- scratch (aliased by liveness)
__device__ float g_xr[BTH], g_xw[BTH], g_xk[BTH], g_xv[BTH], g_xa[BTH], g_xg[BTH];
__device__ float g_r[BTH], g_k[BTH], g_v0[BTH];
__device__ float g_hw[BT*64], g_hv[BT*64], g_ha[BT*64], g_hg[BT*160];
__device__ float g_wl[BTH], g_vl[BTH], g_al[BTH], g_gl[BTH];

#define g_rH  g_xr
#define g_wHe g_xw
#define g_kH  g_xk
#define g_vH  g_xv
#define g_aH  g_xa
#define g_bH  g_xg
#define g_oH  g_wl
#define g_y   g_vl

// ---------------------------------------------------------------- helpers
__device__ __forceinline__ uint32_t smem_u32(const void* p) {
    uint32_t a;
    asm("{ .reg .u64 t; cvta.to.shared.u64 t, %1; cvt.u32.u64 %0, t; }" : "=r"(a) : "l"(p));
    return a;
}
__device__ __forceinline__ float warp_sum(float v) {
    #pragma unroll
    for (int o = 16; o > 0; o >>= 1) v += __shfl_xor_sync(0xffffffffu, v, o);
    return v;
}
__device__ __forceinline__ void cvt_split(float2 v, uint32_t& hi, uint32_t& lo) {
    __nv_bfloat162 h = __float22bfloat162_rn(v);
    float2 hf = __bfloat1622float2(h);
    __nv_bfloat162 l = __float22bfloat162_rn(make_float2(v.x - hf.x, v.y - hf.y));
    hi = *(uint32_t*)&h;
    lo = *(uint32_t*)&l;
}

#define STS_V2(addr, x, y) asm volatile("st.shared.v2.u32 [%0], {%1,%2};" :: "r"(addr), "r"(x), "r"(y) : "memory")

#define LDSM_X4(r, addr) \
    asm volatile("ldmatrix.sync.aligned.m8n8.x4.shared.b16 {%0,%1,%2,%3}, [%4];" \
        : "=r"((r)[0]),"=r"((r)[1]),"=r"((r)[2]),"=r"((r)[3]) : "r"(addr))
#define LDSM_X4_T(r, addr) \
    asm volatile("ldmatrix.sync.aligned.m8n8.x4.trans.shared.b16 {%0,%1,%2,%3}, [%4];" \
        : "=r"((r)[0]),"=r"((r)[1]),"=r"((r)[2]),"=r"((r)[3]) : "r"(addr))

#define MMA_BF16(d, a, b) \
    asm volatile("mma.sync.aligned.m16n8k16.row.col.f32.bf16.bf16.f32 " \
        "{%0,%1,%2,%3}, {%4,%5,%6,%7}, {%8,%9}, {%0,%1,%2,%3};" \
        : "+f"((d)[0]),"+f"((d)[1]),"+f"((d)[2]),"+f"((d)[3]) \
        : "r"((a)[0]),"r"((a)[1]),"r"((a)[2]),"r"((a)[3]), "r"((b)[0]),"r"((b)[1]))

// ---------------------------------------------------------------- warp-MMA GEMM (split bf16, 3 passes)
// C[M,N] = A[M,K] @ W[K,N], fp32 in/out. CTA tile 128x128, K-step 32, 8 warps.
// SMEM stage layout: A_hi [128 rows x 80B] | A_lo | B_hi [32 rows x 256B, XOR swz] | B_lo
#define GM_AHI 0u
#define GM_ALO 10240u
#define GM_BHI 20480u
#define GM_BLO 28672u
#define GM_STAGE 36864u
#define GM_SMEM (2*36864 + 1024)

__global__ __launch_bounds__(256)
void gemm_mma(const float* __restrict__ A, const float* __restrict__ W,
              float* __restrict__ C, int M, int N, int K,
              const float* __restrict__ bias, int act) {
    extern __shared__ char dsm[];
    uint32_t sb = (smem_u32(dsm) + 1023u) & ~1023u;

    int tid = threadIdx.x;
    int wid = tid >> 5, lane = tid & 31;
    int wm = wid >> 2, wn = wid & 3;             // warp grid 2x4 -> 64m x 32n
    int m0 = blockIdx.y * 128;
    int n0 = blockIdx.x * 128;

    // global load assignments
    int aM  = tid >> 3;                          // 0..31 (+32*rep)
    int ak4 = tid & 7;                           // k group of 4 floats
    int bK  = tid >> 5;                          // 0..7 (+8*rep)
    int bn4 = tid & 31;                          // n group of 4 floats

    float acc[4][4][4];
    #pragma unroll
    for (int i = 0; i < 4; i++)
        #pragma unroll
        for (int j = 0; j < 4; j++)
            #pragma unroll
            for (int q = 0; q < 4; q++) acc[i][j][q] = 0.f;

    float4 pa[4], pb[4];
    int nt = K >> 5;

    // preload k-tile 0
    #pragma unroll
    for (int rep = 0; rep < 4; ++rep)
        pa[rep] = *(const float4*)(A + (size_t)(m0 + aM + rep * 32) * K + ak4 * 4);
    #pragma unroll
    for (int rep = 0; rep < 4; ++rep) {
        int gn = n0 + bn4 * 4;
        pb[rep] = (gn < N) ? *(const float4*)(W + (size_t)(bK + rep * 8) * N + gn)
                           : make_float4(0.f, 0.f, 0.f, 0.f);
    }

    for (int it = 0; it < nt; ++it) {
        __syncthreads();                          // all done reading buf[it&1] (from it-2)
        uint32_t base = sb + (uint32_t)(it & 1) * GM_STAGE;

        // ---- store prefetched tile to SMEM (bf16 hi/lo)
        #pragma unroll
        for (int rep = 0; rep < 4; ++rep) {
            int m = aM + rep * 32;
            uint32_t h0, l0, h1, l1;
            cvt_split(make_float2(pa[rep].x, pa[rep].y), h0, l0);
            cvt_split(make_float2(pa[rep].z, pa[rep].w), h1, l1);
            uint32_t ad = base + GM_AHI + (uint32_t)(m * 80 + ak4 * 8);
            STS_V2(ad, h0, h1);
            STS_V2(ad + (GM_ALO - GM_AHI), l0, l1);
        }
        #pragma unroll
        for (int rep = 0; rep < 4; ++rep) {
            int k = bK + rep * 8;
            uint32_t h0, l0, h1, l1;
            cvt_split(make_float2(pb[rep].x, pb[rep].y), h0, l0);
            cvt_split(make_float2(pb[rep].z, pb[rep].w), h1, l1);
            int clog = bn4 >> 1;
            uint32_t bd = base + GM_BHI + (uint32_t)(k * 256 + ((clog ^ (k & 7)) * 16) + (bn4 & 1) * 8);
            STS_V2(bd, h0, h1);
            STS_V2(bd + (GM_BLO - GM_BHI), l0, l1);
        }

        // ---- prefetch next k-tile
        if (it + 1 < nt) {
            int k0 = (it + 1) << 5;
            #pragma unroll
            for (int rep = 0; rep < 4; ++rep)
                pa[rep] = *(const float4*)(A + (size_t)(m0 + aM + rep * 32) * K + k0 + ak4 * 4);
            #pragma unroll
            for (int rep = 0; rep < 4; ++rep) {
                int gn = n0 + bn4 * 4;
                pb[rep] = (gn < N) ? *(const float4*)(W + (size_t)(k0 + bK + rep * 8) * N + gn)
                                   : make_float4(0.f, 0.f, 0.f, 0.f);
            }
        }
        __syncthreads();                          // buf[it&1] ready

        // ---- compute: 2 k16 halves, 3 passes (hh, hl, lh)
        #pragma unroll
        for (int h = 0; h < 2; ++h) {
            uint32_t a_hi[16], a_lo[16], b_hi[8], b_lo[8];
            int lrow = lane & 15;
            int lchk = lane >> 4;
            #pragma unroll
            for (int mf = 0; mf < 4; ++mf) {
                int m = wm * 64 + mf * 16 + lrow;
                int c = h * 2 + lchk;
                uint32_t ad = base + GM_AHI + (uint32_t)(m * 80 + c * 16);
                LDSM_X4(&a_hi[mf * 4], ad);
                LDSM_X4(&a_lo[mf * 4], ad + (GM_ALO - GM_AHI));
            }
            int krow = h * 16 + (lane & 15);
            #pragma unroll
            for (int pr = 0; pr < 2; ++pr) {
                int nabs = wn * 32 + pr * 16 + (lane >> 4) * 8;
                int clog = nabs >> 3;
                uint32_t bd = base + GM_BHI + (uint32_t)(krow * 256 + ((clog ^ (krow & 7)) * 16));
                LDSM_X4_T(&b_hi[pr * 4], bd);
                LDSM_X4_T(&b_lo[pr * 4], bd + (GM_BLO - GM_BHI));
            }
            #pragma unroll
            for (int mf = 0; mf < 4; ++mf)
                #pragma unroll
                for (int nf = 0; nf < 4; ++nf) {
                    uint32_t* bh = &b_hi[(nf >> 1) * 4 + (nf & 1) * 2];
                    MMA_BF16(acc[mf][nf], &a_hi[mf * 4], bh);
                }
            #pragma unroll
            for (int mf = 0; mf < 4; ++mf)
                #pragma unroll
                for (int nf = 0; nf < 4; ++nf) {
                    uint32_t* bl = &b_lo[(nf >> 1) * 4 + (nf & 1) * 2];
                    MMA_BF16(acc[mf][nf], &a_hi[mf * 4], bl);
                }
            #pragma unroll
            for (int mf = 0; mf < 4; ++mf)
                #pragma unroll
                for (int nf = 0; nf < 4; ++nf) {
                    uint32_t* bh = &b_hi[(nf >> 1) * 4 + (nf & 1) * 2];
                    MMA_BF16(acc[mf][nf], &a_lo[mf * 4], bh);
                }
        }
    }

    // ---- epilogue: frag -> gmem with bias/activation
    int rbase = lane >> 2;
    int cbase = (lane & 3) * 2;
    #pragma unroll
    for (int mf = 0; mf < 4; ++mf) {
        #pragma unroll
        for (int nf = 0; nf < 4; ++nf) {
            int col = n0 + wn * 32 + nf * 8 + cbase;
            if (col >= N) continue;
            float b0 = 0.f, b1 = 0.f;
            if (bias) { b0 = bias[col]; b1 = bias[col + 1]; }
            #pragma unroll
            for (int half = 0; half < 2; ++half) {
                int row = m0 + wm * 64 + mf * 16 + rbase + half * 8;
                float t0 = acc[mf][nf][half * 2 + 0] + b0;
                float t1 = acc[mf][nf][half * 2 + 1] + b1;
                if (act == 1) { t0 = tanhf(t0); t1 = tanhf(t1); }
                else if (act == 2) {
                    t0 = 1.f / (1.f + __expf(-t0));
                    t1 = 1.f / (1.f + __expf(-t1));
                }
                float2 o = make_float2(t0, t1);
                *(float2*)(C + (size_t)row * N + col) = o;
            }
        }
    }
}

// ---------------------------------------------------------------- kernel: token-shift mixes
__global__ void prep6_kernel(const float* __restrict__ x,
                             const float* __restrict__ mr, const float* __restrict__ mw,
                             const float* __restrict__ mk, const float* __restrict__ mv,
                             const float* __restrict__ ma, const float* __restrict__ mg) {
    int idx = blockIdx.x * blockDim.x + threadIdx.x;
    if (idx >= BTH) return;
    int ch = idx & (Hh - 1);
    int tok = idx >> 10;
    int t = tok & (Tt - 1);
    float xc = x[idx];
    float xp = (t == 0) ? 0.f : x[idx - Hh];
    float d = xp - xc;
    g_xr[idx] = xc + d * mr[ch];
    g_xw[idx] = xc + d * mw[ch];
    g_xk[idx] = xc + d * mk[ch];
    g_xv[idx] = xc + d * mv[ch];
    g_xa[idx] = xc + d * ma[ch];
    g_xg[idx] = xc + d * mg[ch];
}

// ---------------------------------------------------------------- kernel: per-(token,head) prep (8 warps/block)
__global__ __launch_bounds__(256)
void prep_scan_kernel(const float* __restrict__ v_first,
                      const float* __restrict__ k_k,
                      const float* __restrict__ k_a) {
    int bh = blockIdx.x * 8 + (threadIdx.x >> 5);
    int lane = threadIdx.x & 31;
    int tok = bh >> 4;
    int h = bh & 15;
    int b = tok >> 11;
    int t = tok & (Tt - 1);
    int ofs = tok * Hh + h * 64;
    int hofs = (((b * NHh + h) * Tt) + t) * 64;
    int hd0 = h * 64 + lane, hd1 = hd0 + 32;

    float kv0 = g_k[ofs + lane],  kv1 = g_k[ofs + lane + 32];
    float av0 = g_al[ofs + lane], av1 = g_al[ofs + lane + 32];
    float kk0 = kv0 * k_k[hd0],   kk1 = kv1 * k_k[hd1];
    float ss = warp_sum(kk0 * kk0 + kk1 * kk1);
    float inv = 1.f / fmaxf(sqrtf(ss), 1e-12f);

    float r0 = g_r[ofs + lane],   r1 = g_r[ofs + lane + 32];
    float w0 = g_wl[ofs + lane],  w1 = g_wl[ofs + lane + 32];
    float vv0 = g_v0[ofs + lane], vv1 = g_v0[ofs + lane + 32];
    float vl0 = g_vl[ofs + lane], vl1 = g_vl[ofs + lane + 32];
    float vf0 = v_first[ofs + lane], vf1 = v_first[ofs + lane + 32];

    #pragma unroll
    for (int e = 0; e < 2; e++) {
        int d = lane + e * 32;
        float kv = e ? kv1 : kv0;
        float aa = e ? av1 : av0;
        float kkn = (e ? kk1 : kk0) * inv;
        g_aH[hofs + d] = -kkn;
        g_bH[hofs + d] = kkn * aa;
        g_kH[hofs + d] = kv * (1.f + (aa - 1.f) * k_a[h * 64 + d]);
        g_rH[hofs + d] = e ? r1 : r0;
        g_wHe[hofs + d] = __expf(DECAYC * (e ? w1 : w0));
        float v0v = e ? vv1 : vv0;
        g_vH[hofs + d] = v0v + (e ? vl1 : vl0) * ((e ? vf1 : vf0) - v0v);
    }
}

// ---------------------------------------------------------------- kernel: sequential WKV7 scan
__global__ __launch_bounds__(128)
void scan_kernel() {
    int head = blockIdx.x >> 1;
    int half = blockIdx.x & 1;
    size_t base = (size_t)head * Tt * 64;
    int tid = threadIdx.x;
    int v = (tid >> 2) + half * 32;
    int c = tid & 3;
    int co = c * 16;

    __shared__ float sbuf[2][6 * 64];

    const float* srcs[6] = { g_rH + base, g_wHe + base, g_kH + base,
                             g_vH + base, g_aH + base, g_bH + base };
    int e0 = tid, e1 = tid + 128, e2 = tid + 256;
    const float* p0 = srcs[e0 >> 6] + (e0 & 63);
    const float* p1 = srcs[e1 >> 6] + (e1 & 63);
    const float* p2 = srcs[e2 >> 6] + (e2 & 63);

    sbuf[0][e0] = *p0; sbuf[0][e1] = *p1; sbuf[0][e2] = *p2;
    p0 += 64; p1 += 64; p2 += 64;
    __syncthreads();

    float S[16];
    #pragma unroll
    for (int j = 0; j < 16; j++) S[j] = 0.f;

    float* outp = g_oH + base + v;

    for (int t = 0; t < Tt; t++) {
        float* nx = sbuf[(t + 1) & 1];
        if (t + 1 < Tt) {
            nx[e0] = *p0; nx[e1] = *p1; nx[e2] = *p2;
            p0 += 64; p1 += 64; p2 += 64;
        }
        const float* cu = sbuf[t & 1];
        const float* rs = cu;
        const float* ws = cu + 64;
        const float* ks = cu + 128;
        const float* vs = cu + 192;
        const float* as_ = cu + 256;
        const float* bs = cu + 320;

        float sa = 0.f;
        #pragma unroll
        for (int j = 0; j < 16; j++) sa += S[j] * as_[co + j];
        sa += __shfl_xor_sync(0xffffffffu, sa, 1);
        sa += __shfl_xor_sync(0xffffffffu, sa, 2);

        float vt = vs[v];
        float o = 0.f;
        #pragma unroll
        for (int j = 0; j < 16; j++) {
            float s = S[j] * ws[co + j] + sa * bs[co + j] + vt * ks[co + j];
            S[j] = s;
            o += s * rs[co + j];
        }
        o += __shfl_xor_sync(0xffffffffu, o, 1);
        o += __shfl_xor_sync(0xffffffffu, o, 2);
        if (c == 0) outp[(size_t)t * 64] = o;
        __syncthreads();
    }
}

// ---------------------------------------------------------------- kernel: groupnorm + correction + gate (8 warps/block)
__global__ __launch_bounds__(256)
void out_stage_kernel(const float* __restrict__ r_k,
                      const float* __restrict__ gn_w,
                      const float* __restrict__ gn_b) {
    int bh = blockIdx.x * 8 + (threadIdx.x >> 5);
    int lane = threadIdx.x & 31;
    int tok = bh >> 4;
    int h = bh & 15;
    int b = tok >> 11;
    int t = tok & (Tt - 1);
    int ofs = tok * Hh + h * 64;
    int hofs = (((b * NHh + h) * Tt) + t) * 64;

    float o0 = g_oH[hofs + lane], o1 = g_oH[hofs + lane + 32];
    float r0 = g_rH[hofs + lane], r1 = g_rH[hofs + lane + 32];
    float k0 = g_kH[hofs + lane], k1 = g_kH[hofs + lane + 32];
    float v0 = g_vH[hofs + lane], v1 = g_vH[hofs + lane + 32];

    float mu = warp_sum(o0 + o1) * (1.f / 64.f);
    float sq = warp_sum(o0 * o0 + o1 * o1) * (1.f / 64.f);
    float var = sq - mu * mu;
    float rstd = rsqrtf(var + GN_EPS);
    float dot = warp_sum(r0 * k0 * r_k[h * 64 + lane] + r1 * k1 * r_k[h * 64 + lane + 32]);

    #pragma unroll
    for (int e = 0; e < 2; e++) {
        int d = lane + e * 32;
        float oo = e ? o1 : o0;
        float vv = e ? v1 : v0;
        float on = (oo - mu) * rstd * gn_w[h * 64 + d] + gn_b[h * 64 + d];
        g_y[ofs + d] = (on + dot * vv) * g_gl[ofs + d];
    }
}

// ---------------------------------------------------------------- launch
extern "C" void kernel_launch(void* const* d_in, const int* in_sizes, int n_in,
                              void* d_out, int out_size) {
    const float* x       = (const float*)d_in[0];
    const float* v_first = (const float*)d_in[1];
    const float* x_r = (const float*)d_in[2];
    const float* x_w = (const float*)d_in[3];
    const float* x_k = (const float*)d_in[4];
    const float* x_v = (const float*)d_in[5];
    const float* x_a = (const float*)d_in[6];
    const float* x_g = (const float*)d_in[7];
    const float* k_k = (const float*)d_in[8];
    const float* k_a = (const float*)d_in[9];
    const float* r_k = (const float*)d_in[10];
    const float* W_r = (const float*)d_in[11];
    const float* W_k = (const float*)d_in[12];
    const float* W_v = (const float*)d_in[13];
    const float* W_o = (const float*)d_in[14];
    const float* wA  = (const float*)d_in[15];
    const float* wB  = (const float*)d_in[16];
    const float* wb  = (const float*)d_in[17];
    const float* vA  = (const float*)d_in[18];
    const float* vB  = (const float*)d_in[19];
    const float* vb  = (const float*)d_in[20];
    const float* aA  = (const float*)d_in[21];
    const float* aB  = (const float*)d_in[22];
    const float* ab  = (const float*)d_in[23];
    const float* gA  = (const float*)d_in[24];
    const float* gB  = (const float*)d_in[25];
    const float* gn_w = (const float*)d_in[26];
    const float* gn_b = (const float*)d_in[27];
    float* out = (float*)d_out;

    float *p_xr, *p_xw, *p_xk, *p_xv, *p_xa, *p_xg;
    float *p_r, *p_k, *p_v0, *p_hw, *p_hv, *p_ha, *p_hg;
    float *p_wl, *p_vl, *p_al, *p_gl;
    cudaGetSymbolAddress((void**)&p_xr, g_xr);
    cudaGetSymbolAddress((void**)&p_xw, g_xw);
    cudaGetSymbolAddress((void**)&p_xk, g_xk);
    cudaGetSymbolAddress((void**)&p_xv, g_xv);
    cudaGetSymbolAddress((void**)&p_xa, g_xa);
    cudaGetSymbolAddress((void**)&p_xg, g_xg);
    cudaGetSymbolAddress((void**)&p_r,  g_r);
    cudaGetSymbolAddress((void**)&p_k,  g_k);
    cudaGetSymbolAddress((void**)&p_v0, g_v0);
    cudaGetSymbolAddress((void**)&p_hw, g_hw);
    cudaGetSymbolAddress((void**)&p_hv, g_hv);
    cudaGetSymbolAddress((void**)&p_ha, g_ha);
    cudaGetSymbolAddress((void**)&p_hg, g_hg);
    cudaGetSymbolAddress((void**)&p_wl, g_wl);
    cudaGetSymbolAddress((void**)&p_vl, g_vl);
    cudaGetSymbolAddress((void**)&p_al, g_al);
    cudaGetSymbolAddress((void**)&p_gl, g_gl);

    cudaFuncSetAttribute(gemm_mma, cudaFuncAttributeMaxDynamicSharedMemorySize, GM_SMEM);

    // 1) token-shift mixes
    prep6_kernel<<<(BTH + 255) / 256, 256>>>(x, x_r, x_w, x_k, x_v, x_a, x_g);

    // 2) big projections: r, k, v0 (warp MMA, split bf16)
    dim3 gb(Hh / 128, BT / 128);       // (8, 64)
    gemm_mma<<<gb, 256, GM_SMEM>>>(p_xr, W_r, p_r,  BT, Hh, Hh, nullptr, 0);
    gemm_mma<<<gb, 256, GM_SMEM>>>(p_xk, W_k, p_k,  BT, Hh, Hh, nullptr, 0);
    gemm_mma<<<gb, 256, GM_SMEM>>>(p_xv, W_v, p_v0, BT, Hh, Hh, nullptr, 0);

    // 3) LoRA stage 1
    dim3 gs64(1, BT / 128);
    dim3 gs160(2, BT / 128);
    gemm_mma<<<gs64, 256, GM_SMEM>>>(p_xw, wA, p_hw, BT, 64, Hh, nullptr, 1);   // tanh
    gemm_mma<<<gs64, 256, GM_SMEM>>>(p_xv, vA, p_hv, BT, 64, Hh, nullptr, 0);
    gemm_mma<<<gs64, 256, GM_SMEM>>>(p_xa, aA, p_ha, BT, 64, Hh, nullptr, 0);
    gemm_mma<<<gs160, 256, GM_SMEM>>>(p_xg, gA, p_hg, BT, 160, Hh, nullptr, 2); // sigmoid

    // 4) LoRA stage 2
    gemm_mma<<<gb, 256, GM_SMEM>>>(p_hw, wB, p_wl, BT, Hh, 64,  wb, 2);
    gemm_mma<<<gb, 256, GM_SMEM>>>(p_hv, vB, p_vl, BT, Hh, 64,  vb, 2);
    gemm_mma<<<gb, 256, GM_SMEM>>>(p_ha, aB, p_al, BT, Hh, 64,  ab, 2);
    gemm_mma<<<gb, 256, GM_SMEM>>>(p_hg, gB, p_gl, BT, Hh, 160, nullptr, 0);

    // 5) per-token/head prep into head layout (x-bufs now dead -> reused)
    prep_scan_kernel<<<BT * NHh / 8, 256>>>(v_first, k_k, k_a);

    // 6) sequential scan (writes oH = g_wl, dead)
    scan_kernel<<<Bb * NHh * 2, 128>>>();

    // 7) groupnorm + correction + gate (writes y = g_vl, dead)
    out_stage_kernel<<<BT * NHh / 8, 256>>>(r_k, gn_w, gn_b);

    // 8) output projection
    float* p_y;
    cudaGetSymbolAddress((void**)&p_y, g_vl);
    gemm_mma<<<gb, 256, GM_SMEM>>>(p_y, W_o, out, BT, Hh, Hh, nullptr, 0);

    (void)in_sizes; (void)n_in; (void)out_size;
}

// round 6
// speedup vs baseline: 3.5517x; 2.6343x over previous
#include <cuda_runtime.h>
#include <cuda_bf16.h>
#include <math.h>
#include <stdint.h>

// ---------------------------------------------------------------- constants
#define Bb   4
#define Tt   2048
#define Hh   1024
#define NHh  16
#define HDh  64
#define BT   (Bb*Tt)          // 8192 tokens
#define BTH  (BT*Hh)          // 8388608
#define DECAYC (-0.6065306597126334f)
#define GN_EPS (HDh*1e-5f)    // 6.4e-4

// ---------------------------------------------------------------- scratch (aliased by liveness)
__device__ __align__(128) float g_xr[BTH], g_xw[BTH], g_xk[BTH], g_xv[BTH], g_xa[BTH], g_xg[BTH];
__device__ __align__(128) float g_r[BTH], g_k[BTH], g_v0[BTH];
__device__ __align__(128) float g_hw[BT*64], g_hv[BT*64], g_ha[BT*64], g_hg[BT*160];
__device__ __align__(128) float g_wl[BTH], g_vl[BTH], g_al[BTH], g_gl[BTH];

// weight split scratch (bf16 hi/lo planes, per-weight: hi at off, lo at off+size)
#define SZ_BIG 1048576
#define SZ_LORA 65536
#define SZ_G  163840
#define OFF_WR 0
#define OFF_WK 2097152
#define OFF_WV 4194304
#define OFF_WO 6291456
#define OFF_wA 8388608
#define OFF_vA 8519680
#define OFF_aA 8650752
#define OFF_gA 8781824
#define OFF_wB 9109504
#define OFF_vB 9240576
#define OFF_aB 9371648
#define OFF_gB 9502720
#define WSPLIT_TOTAL 9830400
__device__ __align__(128) __nv_bfloat16 g_wsplit[WSPLIT_TOTAL];

#define g_rH  g_xr
#define g_wHe g_xw
#define g_kH  g_xk
#define g_vH  g_xv
#define g_aH  g_xa
#define g_bH  g_xg
#define g_oH  g_wl
#define g_y   g_vl

// ---------------------------------------------------------------- helpers
__device__ __forceinline__ uint32_t smem_u32(const void* p) {
    uint32_t a;
    asm("{ .reg .u64 t; cvta.to.shared.u64 t, %1; cvt.u32.u64 %0, t; }" : "=r"(a) : "l"(p));
    return a;
}
__device__ __forceinline__ float warp_sum(float v) {
    #pragma unroll
    for (int o = 16; o > 0; o >>= 1) v += __shfl_xor_sync(0xffffffffu, v, o);
    return v;
}
__device__ __forceinline__ void cvt_split2(float a, float b, uint32_t& hi, uint32_t& lo) {
    __nv_bfloat162 h = __float22bfloat162_rn(make_float2(a, b));
    float2 hf = __bfloat1622float2(h);
    __nv_bfloat162 l = __float22bfloat162_rn(make_float2(a - hf.x, b - hf.y));
    hi = *(uint32_t*)&h;
    lo = *(uint32_t*)&l;
}

#define CP_A16(dst, src)      asm volatile("cp.async.cg.shared.global [%0], [%1], 16;" :: "r"(dst), "l"(src) : "memory")
#define CP_A16Z(dst, src, sz) asm volatile("cp.async.cg.shared.global [%0], [%1], 16, %2;" :: "r"(dst), "l"(src), "r"(sz) : "memory")
#define CP_COMMIT()           asm volatile("cp.async.commit_group;" ::: "memory")
#define CP_WAIT(n)            asm volatile("cp.async.wait_group %0;" :: "n"(n) : "memory")

#define LDSM_X4(r, addr) \
    asm volatile("ldmatrix.sync.aligned.m8n8.x4.shared.b16 {%0,%1,%2,%3}, [%4];" \
        : "=r"((r)[0]),"=r"((r)[1]),"=r"((r)[2]),"=r"((r)[3]) : "r"(addr))
#define LDSM_X4_T(r, addr) \
    asm volatile("ldmatrix.sync.aligned.m8n8.x4.trans.shared.b16 {%0,%1,%2,%3}, [%4];" \
        : "=r"((r)[0]),"=r"((r)[1]),"=r"((r)[2]),"=r"((r)[3]) : "r"(addr))

#define MMA_BF16(d, a, b) \
    asm volatile("mma.sync.aligned.m16n8k16.row.col.f32.bf16.bf16.f32 " \
        "{%0,%1,%2,%3}, {%4,%5,%6,%7}, {%8,%9}, {%0,%1,%2,%3};" \
        : "+f"((d)[0]),"+f"((d)[1]),"+f"((d)[2]),"+f"((d)[3]) \
        : "r"((a)[0]),"r"((a)[1]),"r"((a)[2]),"r"((a)[3]), "r"((b)[0]),"r"((b)[1]))

// ---------------------------------------------------------------- batched warp-MMA GEMM (pre-split bf16, 3 passes)
// C = A @ W. CTA tile 128x128, K-step 32, 8 warps. blockIdx.z selects operand set.
// SMEM stage: A_hi[128x80B] | A_lo | B_hi[32x256B xor-swz] | B_lo
#define G_STAGE 36864u
#define G_SMEM  (2*36864 + 1024)

struct GemmZ {
    const __nv_bfloat16 *Ahi, *Alo, *Bhi, *Blo;
    float* C;
    __nv_bfloat16 *Chi, *Clo;
    const float* bias;
    int act;            // 0 none, 1 tanh, 2 sigmoid
};
struct GemmBatch { GemmZ z[3]; };

__global__ __launch_bounds__(256, 2)
void gemm_mma(GemmBatch gb, int M, int N, int K, int split_out) {
    extern __shared__ char dsm[];
    uint32_t sb = (smem_u32(dsm) + 1023u) & ~1023u;
    GemmZ zz = gb.z[blockIdx.z];

    int tid = threadIdx.x;
    int wid = tid >> 5, lane = tid & 31;
    int wm = wid >> 2, wn = wid & 3;
    int m0 = blockIdx.y * 128;
    int n0 = blockIdx.x * 128;
    int nt = K >> 5;

    auto issue = [&](int it) {
        uint32_t base = sb + (uint32_t)(it & 1) * G_STAGE;
        int k0 = it << 5;
        #pragma unroll
        for (int s = 0; s < 2; ++s) {
            int ca = tid + s * 256;
            int row = ca >> 2, cc = ca & 3;
            size_t so = (size_t)(m0 + row) * K + k0 + cc * 8;
            uint32_t da = base + (uint32_t)(row * 80 + cc * 16);
            CP_A16(da, zz.Ahi + so);
            CP_A16(da + 10240u, zz.Alo + so);
        }
        #pragma unroll
        for (int s = 0; s < 2; ++s) {
            int cb = tid + s * 256;
            int kk = cb >> 4, j = cb & 15;
            int gn = n0 + j * 8;
            uint32_t sz = (gn < N) ? 16u : 0u;
            size_t so = (size_t)(k0 + kk) * N + ((gn < N) ? gn : 0);
            uint32_t db = base + 20480u + (uint32_t)(kk * 256 + ((j ^ (kk & 7)) * 16));
            CP_A16Z(db, zz.Bhi + so, sz);
            CP_A16Z(db + 8192u, zz.Blo + so, sz);
        }
        CP_COMMIT();
    };

    float acc[4][4][4];
    #pragma unroll
    for (int i = 0; i < 4; i++)
        #pragma unroll
        for (int j = 0; j < 4; j++)
            #pragma unroll
            for (int q = 0; q < 4; q++) acc[i][j][q] = 0.f;

    issue(0);
    for (int it = 0; it < nt; ++it) {
        if (it + 1 < nt) { issue(it + 1); CP_WAIT(1); }
        else             { CP_WAIT(0); }
        __syncthreads();
        uint32_t base = sb + (uint32_t)(it & 1) * G_STAGE;

        #pragma unroll
        for (int h = 0; h < 2; ++h) {
            uint32_t a_hi[16], b_hi[8], tmp[16];
            int lrow = lane & 15, lchk = lane >> 4;
            uint32_t ad[4];
            #pragma unroll
            for (int mf = 0; mf < 4; ++mf) {
                ad[mf] = base + (uint32_t)((wm * 64 + mf * 16 + lrow) * 80 + (h * 2 + lchk) * 16);
                LDSM_X4(&a_hi[mf * 4], ad[mf]);
            }
            int krow = h * 16 + (lane & 15);
            uint32_t bd[2];
            #pragma unroll
            for (int pr = 0; pr < 2; ++pr) {
                int nabs = wn * 32 + pr * 16 + (lane >> 4) * 8;
                int clog = nabs >> 3;
                bd[pr] = base + 20480u + (uint32_t)(krow * 256 + ((clog ^ (krow & 7)) * 16));
                LDSM_X4_T(&b_hi[pr * 4], bd[pr]);
            }
            // pass hh
            #pragma unroll
            for (int mf = 0; mf < 4; ++mf)
                #pragma unroll
                for (int nf = 0; nf < 4; ++nf)
                    MMA_BF16(acc[mf][nf], &a_hi[mf * 4], (&b_hi[(nf >> 1) * 4 + (nf & 1) * 2]));
            // a_lo -> tmp, pass lh
            #pragma unroll
            for (int mf = 0; mf < 4; ++mf) LDSM_X4(&tmp[mf * 4], ad[mf] + 10240u);
            #pragma unroll
            for (int mf = 0; mf < 4; ++mf)
                #pragma unroll
                for (int nf = 0; nf < 4; ++nf)
                    MMA_BF16(acc[mf][nf], &tmp[mf * 4], (&b_hi[(nf >> 1) * 4 + (nf & 1) * 2]));
            // b_lo -> reuse b_hi regs, pass hl
            #pragma unroll
            for (int pr = 0; pr < 2; ++pr) LDSM_X4_T(&b_hi[pr * 4], bd[pr] + 8192u);
            #pragma unroll
            for (int mf = 0; mf < 4; ++mf)
                #pragma unroll
                for (int nf = 0; nf < 4; ++nf)
                    MMA_BF16(acc[mf][nf], &a_hi[mf * 4], (&b_hi[(nf >> 1) * 4 + (nf & 1) * 2]));
        }
        __syncthreads();
    }

    // ---- epilogue
    int rbase = lane >> 2;
    int cbase = (lane & 3) * 2;
    #pragma unroll
    for (int mf = 0; mf < 4; ++mf) {
        #pragma unroll
        for (int nf = 0; nf < 4; ++nf) {
            int col = n0 + wn * 32 + nf * 8 + cbase;
            if (col >= N) continue;
            float b0 = 0.f, b1 = 0.f;
            if (zz.bias) { b0 = zz.bias[col]; b1 = zz.bias[col + 1]; }
            #pragma unroll
            for (int half = 0; half < 2; ++half) {
                int row = m0 + wm * 64 + mf * 16 + rbase + half * 8;
                float t0 = acc[mf][nf][half * 2 + 0] + b0;
                float t1 = acc[mf][nf][half * 2 + 1] + b1;
                if (zz.act == 1) { t0 = tanhf(t0); t1 = tanhf(t1); }
                else if (zz.act == 2) {
                    t0 = 1.f / (1.f + __expf(-t0));
                    t1 = 1.f / (1.f + __expf(-t1));
                }
                if (!split_out) {
                    *(float2*)(zz.C + (size_t)row * N + col) = make_float2(t0, t1);
                } else {
                    uint32_t hw, lw;
                    cvt_split2(t0, t1, hw, lw);
                    *(uint32_t*)(zz.Chi + (size_t)row * N + col) = hw;
                    *(uint32_t*)(zz.Clo + (size_t)row * N + col) = lw;
                }
            }
        }
    }
}

// ---------------------------------------------------------------- kernel: weight split conversion
__global__ void conv_split_kernel(const float* __restrict__ src,
                                  __nv_bfloat16* __restrict__ hi,
                                  __nv_bfloat16* __restrict__ lo, int npairs) {
    int p = blockIdx.x * blockDim.x + threadIdx.x;
    if (p >= npairs) return;
    float2 v = ((const float2*)src)[p];
    uint32_t hw, lw;
    cvt_split2(v.x, v.y, hw, lw);
    ((uint32_t*)hi)[p] = hw;
    ((uint32_t*)lo)[p] = lw;
}

// ---------------------------------------------------------------- kernel: token-shift mixes -> bf16 hi/lo planes
__global__ void prep6_kernel(const float* __restrict__ x,
                             const float* __restrict__ mr, const float* __restrict__ mw,
                             const float* __restrict__ mk, const float* __restrict__ mv,
                             const float* __restrict__ ma, const float* __restrict__ mg) {
    int p = blockIdx.x * blockDim.x + threadIdx.x;
    if (p >= BTH / 2) return;
    int idx = p * 2;
    int ch = idx & (Hh - 1);
    int tok = idx >> 10;
    int t = tok & (Tt - 1);
    float x0 = x[idx], x1 = x[idx + 1];
    float d0 = ((t == 0) ? 0.f : x[idx - Hh]) - x0;
    float d1 = ((t == 0) ? 0.f : x[idx - Hh + 1]) - x1;

    float* dsts[6] = { g_xr, g_xw, g_xk, g_xv, g_xa, g_xg };
    const float* ms[6] = { mr, mw, mk, mv, ma, mg };
    #pragma unroll
    for (int i = 0; i < 6; ++i) {
        float v0 = x0 + d0 * ms[i][ch];
        float v1 = x1 + d1 * ms[i][ch + 1];
        uint32_t hw, lw;
        cvt_split2(v0, v1, hw, lw);
        __nv_bfloat16* base = (__nv_bfloat16*)dsts[i];
        ((uint32_t*)base)[p] = hw;
        ((uint32_t*)(base + BTH))[p] = lw;
    }
}

// ---------------------------------------------------------------- kernel: per-(token,head) prep (8 warps/block)
__global__ __launch_bounds__(256)
void prep_scan_kernel(const float* __restrict__ v_first,
                      const float* __restrict__ k_k,
                      const float* __restrict__ k_a) {
    int bh = blockIdx.x * 8 + (threadIdx.x >> 5);
    int lane = threadIdx.x & 31;
    int tok = bh >> 4;
    int h = bh & 15;
    int b = tok >> 11;
    int t = tok & (Tt - 1);
    int ofs = tok * Hh + h * 64;
    int hofs = (((b * NHh + h) * Tt) + t) * 64;
    int hd0 = h * 64 + lane, hd1 = hd0 + 32;

    float kv0 = g_k[ofs + lane],  kv1 = g_k[ofs + lane + 32];
    float av0 = g_al[ofs + lane], av1 = g_al[ofs + lane + 32];
    float kk0 = kv0 * k_k[hd0],   kk1 = kv1 * k_k[hd1];
    float ss = warp_sum(kk0 * kk0 + kk1 * kk1);
    float inv = 1.f / fmaxf(sqrtf(ss), 1e-12f);

    float r0 = g_r[ofs + lane],   r1 = g_r[ofs + lane + 32];
    float w0 = g_wl[ofs + lane],  w1 = g_wl[ofs + lane + 32];
    float vv0 = g_v0[ofs + lane], vv1 = g_v0[ofs + lane + 32];
    float vl0 = g_vl[ofs + lane], vl1 = g_vl[ofs + lane + 32];
    float vf0 = v_first[ofs + lane], vf1 = v_first[ofs + lane + 32];

    #pragma unroll
    for (int e = 0; e < 2; e++) {
        int d = lane + e * 32;
        float kv = e ? kv1 : kv0;
        float aa = e ? av1 : av0;
        float kkn = (e ? kk1 : kk0) * inv;
        g_aH[hofs + d] = -kkn;
        g_bH[hofs + d] = kkn * aa;
        g_kH[hofs + d] = kv * (1.f + (aa - 1.f) * k_a[h * 64 + d]);
        g_rH[hofs + d] = e ? r1 : r0;
        g_wHe[hofs + d] = __expf(DECAYC * (e ? w1 : w0));
        float v0v = e ? vv1 : vv0;
        g_vH[hofs + d] = v0v + (e ? vl1 : vl0) * ((e ? vf1 : vf0) - v0v);
    }
}

// ---------------------------------------------------------------- kernel: WKV7 scan, cp.async ring depth 8
__global__ __launch_bounds__(128)
void scan_kernel() {
    int head = blockIdx.x >> 1;
    int half = blockIdx.x & 1;
    size_t base = (size_t)head * Tt * 64;
    int tid = threadIdx.x;
    int v = (tid >> 2) + half * 32;
    int c = tid & 3;
    int co = c * 16;

    __shared__ __align__(16) float ring[8][384];

    const float* srcs[6] = { g_rH + base, g_wHe + base, g_kH + base,
                             g_vH + base, g_aH + base, g_bH + base };
    bool active = tid < 96;
    int arr = tid >> 4, cc = tid & 15;
    const float* src0 = srcs[active ? arr : 0] + cc * 4;
    uint32_t dofs = (uint32_t)(arr * 256 + cc * 16);

    auto issue = [&](int tt, int slot) {
        if (active) CP_A16(smem_u32(&ring[slot][0]) + dofs, src0 + (size_t)tt * 64);
        CP_COMMIT();
    };

    #pragma unroll
    for (int s = 0; s < 7; ++s) issue(s, s);

    float S[16];
    #pragma unroll
    for (int j = 0; j < 16; j++) S[j] = 0.f;

    float* outp = g_oH + base + v;

    for (int t = 0; t < Tt; ++t) {
        int tt = (t + 7 < Tt) ? t + 7 : Tt - 1;
        issue(tt, (t + 7) & 7);
        CP_WAIT(7);
        __syncthreads();

        const float* cu = ring[t & 7];
        float aL[16], wL[16], kL[16], rL[16], bL[16];
        #pragma unroll
        for (int q = 0; q < 4; ++q) {
            *(float4*)(rL + q * 4) = *(const float4*)(cu + co + q * 4);
            *(float4*)(wL + q * 4) = *(const float4*)(cu + 64 + co + q * 4);
            *(float4*)(kL + q * 4) = *(const float4*)(cu + 128 + co + q * 4);
            *(float4*)(aL + q * 4) = *(const float4*)(cu + 256 + co + q * 4);
            *(float4*)(bL + q * 4) = *(const float4*)(cu + 320 + co + q * 4);
        }
        float vt = cu[192 + v];

        float sa = 0.f;
        #pragma unroll
        for (int j = 0; j < 16; j++) sa += S[j] * aL[j];
        sa += __shfl_xor_sync(0xffffffffu, sa, 1);
        sa += __shfl_xor_sync(0xffffffffu, sa, 2);

        float o = 0.f;
        #pragma unroll
        for (int j = 0; j < 16; j++) {
            float s = S[j] * wL[j] + sa * bL[j] + vt * kL[j];
            S[j] = s;
            o += s * rL[j];
        }
        o += __shfl_xor_sync(0xffffffffu, o, 1);
        o += __shfl_xor_sync(0xffffffffu, o, 2);
        if (c == 0) outp[(size_t)t * 64] = o;
        __syncthreads();
    }
}

// ---------------------------------------------------------------- kernel: groupnorm + corr + gate -> y bf16 planes
__global__ __launch_bounds__(256)
void out_stage_kernel(const float* __restrict__ r_k,
                      const float* __restrict__ gn_w,
                      const float* __restrict__ gn_b) {
    int bh = blockIdx.x * 8 + (threadIdx.x >> 5);
    int lane = threadIdx.x & 31;
    int tok = bh >> 4;
    int h = bh & 15;
    int b = tok >> 11;
    int t = tok & (Tt - 1);
    int ofs = tok * Hh + h * 64;
    int hofs = (((b * NHh + h) * Tt) + t) * 64;
    int d0 = lane * 2, d1 = d0 + 1;

    float o0 = g_oH[hofs + d0], o1 = g_oH[hofs + d1];
    float r0 = g_rH[hofs + d0], r1 = g_rH[hofs + d1];
    float k0 = g_kH[hofs + d0], k1 = g_kH[hofs + d1];
    float v0 = g_vH[hofs + d0], v1 = g_vH[hofs + d1];

    float mu = warp_sum(o0 + o1) * (1.f / 64.f);
    float sq = warp_sum(o0 * o0 + o1 * o1) * (1.f / 64.f);
    float var = sq - mu * mu;
    float rstd = rsqrtf(var + GN_EPS);
    float dot = warp_sum(r0 * k0 * r_k[h * 64 + d0] + r1 * k1 * r_k[h * 64 + d1]);

    float gl0 = g_gl[ofs + d0], gl1 = g_gl[ofs + d1];
    float on0 = (o0 - mu) * rstd * gn_w[h * 64 + d0] + gn_b[h * 64 + d0];
    float on1 = (o1 - mu) * rstd * gn_w[h * 64 + d1] + gn_b[h * 64 + d1];
    float y0 = (on0 + dot * v0) * gl0;
    float y1 = (on1 + dot * v1) * gl1;

    uint32_t hw, lw;
    cvt_split2(y0, y1, hw, lw);
    __nv_bfloat16* ybase = (__nv_bfloat16*)g_y;
    ((uint32_t*)ybase)[(ofs + d0) >> 1] = hw;
    ((uint32_t*)(ybase + BTH))[(ofs + d0) >> 1] = lw;
}

// ---------------------------------------------------------------- launch
extern "C" void kernel_launch(void* const* d_in, const int* in_sizes, int n_in,
                              void* d_out, int out_size) {
    const float* x       = (const float*)d_in[0];
    const float* v_first = (const float*)d_in[1];
    const float* x_r = (const float*)d_in[2];
    const float* x_w = (const float*)d_in[3];
    const float* x_k = (const float*)d_in[4];
    const float* x_v = (const float*)d_in[5];
    const float* x_a = (const float*)d_in[6];
    const float* x_g = (const float*)d_in[7];
    const float* k_k = (const float*)d_in[8];
    const float* k_a = (const float*)d_in[9];
    const float* r_k = (const float*)d_in[10];
    const float* W_r = (const float*)d_in[11];
    const float* W_k = (const float*)d_in[12];
    const float* W_v = (const float*)d_in[13];
    const float* W_o = (const float*)d_in[14];
    const float* wA  = (const float*)d_in[15];
    const float* wB  = (const float*)d_in[16];
    const float* wb  = (const float*)d_in[17];
    const float* vA  = (const float*)d_in[18];
    const float* vB  = (const float*)d_in[19];
    const float* vb  = (const float*)d_in[20];
    const float* aA  = (const float*)d_in[21];
    const float* aB  = (const float*)d_in[22];
    const float* ab  = (const float*)d_in[23];
    const float* gA  = (const float*)d_in[24];
    const float* gB  = (const float*)d_in[25];
    const float* gn_w = (const float*)d_in[26];
    const float* gn_b = (const float*)d_in[27];
    float* out = (float*)d_out;

    float *p_xr, *p_xw, *p_xk, *p_xv, *p_xa, *p_xg;
    float *p_r, *p_k, *p_v0, *p_hw, *p_hv, *p_ha, *p_hg;
    float *p_wl, *p_vl, *p_al, *p_gl;
    __nv_bfloat16* p_ws;
    cudaGetSymbolAddress((void**)&p_xr, g_xr);
    cudaGetSymbolAddress((void**)&p_xw, g_xw);
    cudaGetSymbolAddress((void**)&p_xk, g_xk);
    cudaGetSymbolAddress((void**)&p_xv, g_xv);
    cudaGetSymbolAddress((void**)&p_xa, g_xa);
    cudaGetSymbolAddress((void**)&p_xg, g_xg);
    cudaGetSymbolAddress((void**)&p_r,  g_r);
    cudaGetSymbolAddress((void**)&p_k,  g_k);
    cudaGetSymbolAddress((void**)&p_v0, g_v0);
    cudaGetSymbolAddress((void**)&p_hw, g_hw);
    cudaGetSymbolAddress((void**)&p_hv, g_hv);
    cudaGetSymbolAddress((void**)&p_ha, g_ha);
    cudaGetSymbolAddress((void**)&p_hg, g_hg);
    cudaGetSymbolAddress((void**)&p_wl, g_wl);
    cudaGetSymbolAddress((void**)&p_vl, g_vl);
    cudaGetSymbolAddress((void**)&p_al, g_al);
    cudaGetSymbolAddress((void**)&p_gl, g_gl);
    cudaGetSymbolAddress((void**)&p_ws, g_wsplit);

    cudaFuncSetAttribute(gemm_mma, cudaFuncAttributeMaxDynamicSharedMemorySize, G_SMEM);

    // ---- weight splits (hi at off, lo at off+size)
    struct WC { const float* src; int off; int sz; };
    WC wcs[12] = {
        {W_r, OFF_WR, SZ_BIG}, {W_k, OFF_WK, SZ_BIG}, {W_v, OFF_WV, SZ_BIG}, {W_o, OFF_WO, SZ_BIG},
        {wA, OFF_wA, SZ_LORA}, {vA, OFF_vA, SZ_LORA}, {aA, OFF_aA, SZ_LORA}, {gA, OFF_gA, SZ_G},
        {wB, OFF_wB, SZ_LORA}, {vB, OFF_vB, SZ_LORA}, {aB, OFF_aB, SZ_LORA}, {gB, OFF_gB, SZ_G},
    };
    for (int i = 0; i < 12; ++i) {
        int np = wcs[i].sz / 2;
        conv_split_kernel<<<(np + 255) / 256, 256>>>(wcs[i].src, p_ws + wcs[i].off,
                                                     p_ws + wcs[i].off + wcs[i].sz, np);
    }

    // ---- token-shift mixes (writes bf16 planes)
    prep6_kernel<<<(BTH / 2 + 255) / 256, 256>>>(x, x_r, x_w, x_k, x_v, x_a, x_g);

    auto planes = [&](float* f) {
        return (__nv_bfloat16*)f;
    };
    GemmZ Z0 = {};

    // ---- big3 batched: r, k, v0
    {
        GemmBatch gbm = {};
        __nv_bfloat16* a[3] = { planes(p_xr), planes(p_xk), planes(p_xv) };
        int woff[3] = { OFF_WR, OFF_WK, OFF_WV };
        float* cc[3] = { p_r, p_k, p_v0 };
        for (int i = 0; i < 3; ++i) {
            gbm.z[i] = Z0;
            gbm.z[i].Ahi = a[i]; gbm.z[i].Alo = a[i] + BTH;
            gbm.z[i].Bhi = p_ws + woff[i]; gbm.z[i].Blo = p_ws + woff[i] + SZ_BIG;
            gbm.z[i].C = cc[i];
        }
        gemm_mma<<<dim3(8, 64, 3), 256, G_SMEM>>>(gbm, BT, 1024, 1024, 0);
    }
    // ---- LoRA stage1 batched (N=64): hw(tanh), hv, ha  [split outputs]
    {
        GemmBatch gbm = {};
        __nv_bfloat16* a[3] = { planes(p_xw), planes(p_xv), planes(p_xa) };
        int woff[3] = { OFF_wA, OFF_vA, OFF_aA };
        float* cc[3] = { p_hw, p_hv, p_ha };
        int act[3] = { 1, 0, 0 };
        for (int i = 0; i < 3; ++i) {
            gbm.z[i] = Z0;
            gbm.z[i].Ahi = a[i]; gbm.z[i].Alo = a[i] + BTH;
            gbm.z[i].Bhi = p_ws + woff[i]; gbm.z[i].Blo = p_ws + woff[i] + SZ_LORA;
            gbm.z[i].Chi = planes(cc[i]); gbm.z[i].Clo = planes(cc[i]) + BT * 64;
            gbm.z[i].act = act[i];
        }
        gemm_mma<<<dim3(1, 64, 3), 256, G_SMEM>>>(gbm, BT, 64, 1024, 1);
    }
    // ---- gA stage1 (N=160, sigmoid, split out)
    {
        GemmBatch gbm = {};
        gbm.z[0] = Z0;
        gbm.z[0].Ahi = planes(p_xg); gbm.z[0].Alo = planes(p_xg) + BTH;
        gbm.z[0].Bhi = p_ws + OFF_gA; gbm.z[0].Blo = p_ws + OFF_gA + SZ_G;
        gbm.z[0].Chi = planes(p_hg); gbm.z[0].Clo = planes(p_hg) + BT * 160;
        gbm.z[0].act = 2;
        gemm_mma<<<dim3(2, 64, 1), 256, G_SMEM>>>(gbm, BT, 160, 1024, 1);
    }
    // ---- stage2 batched (K=64): wl, vl, al (sigmoid + bias)
    {
        GemmBatch gbm = {};
        float* a[3] = { p_hw, p_hv, p_ha };
        int woff[3] = { OFF_wB, OFF_vB, OFF_aB };
        float* cc[3] = { p_wl, p_vl, p_al };
        const float* bias[3] = { wb, vb, ab };
        for (int i = 0; i < 3; ++i) {
            gbm.z[i] = Z0;
            gbm.z[i].Ahi = planes(a[i]); gbm.z[i].Alo = planes(a[i]) + BT * 64;
            gbm.z[i].Bhi = p_ws + woff[i]; gbm.z[i].Blo = p_ws + woff[i] + SZ_LORA;
            gbm.z[i].C = cc[i]; gbm.z[i].bias = bias[i]; gbm.z[i].act = 2;
        }
        gemm_mma<<<dim3(8, 64, 3), 256, G_SMEM>>>(gbm, BT, 1024, 64, 0);
    }
    // ---- gB stage2 (K=160): gl
    {
        GemmBatch gbm = {};
        gbm.z[0] = Z0;
        gbm.z[0].Ahi = planes(p_hg); gbm.z[0].Alo = planes(p_hg) + BT * 160;
        gbm.z[0].Bhi = p_ws + OFF_gB; gbm.z[0].Blo = p_ws + OFF_gB + SZ_G;
        gbm.z[0].C = p_gl;
        gemm_mma<<<dim3(8, 64, 1), 256, G_SMEM>>>(gbm, BT, 1024, 160, 0);
    }

    // ---- head-layout prep (x-bufs dead -> reused)
    prep_scan_kernel<<<BT * NHh / 8, 256>>>(v_first, k_k, k_a);

    // ---- sequential scan
    scan_kernel<<<Bb * NHh * 2, 128>>>();

    // ---- groupnorm + corr + gate -> y bf16 planes (in g_vl, dead)
    out_stage_kernel<<<BT * NHh / 8, 256>>>(r_k, gn_w, gn_b);

    // ---- output projection
    {
        GemmBatch gbm = {};
        gbm.z[0] = Z0;
        gbm.z[0].Ahi = planes(p_vl); gbm.z[0].Alo = planes(p_vl) + BTH;
        gbm.z[0].Bhi = p_ws + OFF_WO; gbm.z[0].Blo = p_ws + OFF_WO + SZ_BIG;
        gbm.z[0].C = out;
        gemm_mma<<<dim3(8, 64, 1), 256, G_SMEM>>>(gbm, BT, 1024, 1024, 0);
    }

    (void)in_sizes; (void)n_in; (void)out_size;
}

// round 7
// speedup vs baseline: 3.6136x; 1.0174x over previous
#include <cuda_runtime.h>
#include <cuda_bf16.h>
#include <math.h>
#include <stdint.h>

// ---------------------------------------------------------------- constants
#define Bb   4
#define Tt   2048
#define Hh   1024
#define NHh  16
#define HDh  64
#define BT   (Bb*Tt)          // 8192 tokens
#define BTH  (BT*Hh)          // 8388608
#define DECAYC (-0.6065306597126334f)
#define GN_EPS (HDh*1e-5f)    // 6.4e-4

// ---------------------------------------------------------------- scratch (aliased by liveness)
__device__ __align__(128) float g_xr[BTH], g_xw[BTH], g_xk[BTH], g_xv[BTH], g_xa[BTH], g_xg[BTH];
__device__ __align__(128) float g_r[BTH], g_k[BTH], g_v0[BTH];
__device__ __align__(128) float g_hw[BT*64], g_hv[BT*64], g_ha[BT*64], g_hg[BT*160];
__device__ __align__(128) float g_wl[BTH], g_vl[BTH], g_al[BTH], g_gl[BTH];

// weight split scratch (bf16 hi/lo planes, per-weight: hi at off, lo at off+size)
#define SZ_BIG 1048576
#define SZ_LORA 65536
#define SZ_G  163840
#define OFF_WR 0
#define OFF_WK 2097152
#define OFF_WV 4194304
#define OFF_WO 6291456
#define OFF_wA 8388608
#define OFF_vA 8519680
#define OFF_aA 8650752
#define OFF_gA 8781824
#define OFF_wB 9109504
#define OFF_vB 9240576
#define OFF_aB 9371648
#define OFF_gB 9502720
#define WSPLIT_TOTAL 9830400
__device__ __align__(128) __nv_bfloat16 g_wsplit[WSPLIT_TOTAL];

#define g_rH  g_xr
#define g_wHe g_xw
#define g_kH  g_xk
#define g_vH  g_xv
#define g_aH  g_xa
#define g_bH  g_xg
#define g_oH  g_wl
#define g_y   g_vl

// ---------------------------------------------------------------- helpers
__device__ __forceinline__ uint32_t smem_u32(const void* p) {
    uint32_t a;
    asm("{ .reg .u64 t; cvta.to.shared.u64 t, %1; cvt.u32.u64 %0, t; }" : "=r"(a) : "l"(p));
    return a;
}
__device__ __forceinline__ float warp_sum(float v) {
    #pragma unroll
    for (int o = 16; o > 0; o >>= 1) v += __shfl_xor_sync(0xffffffffu, v, o);
    return v;
}
__device__ __forceinline__ void cvt_split2(float a, float b, uint32_t& hi, uint32_t& lo) {
    __nv_bfloat162 h = __float22bfloat162_rn(make_float2(a, b));
    float2 hf = __bfloat1622float2(h);
    __nv_bfloat162 l = __float22bfloat162_rn(make_float2(a - hf.x, b - hf.y));
    hi = *(uint32_t*)&h;
    lo = *(uint32_t*)&l;
}

#define CP_A16(dst, src)      asm volatile("cp.async.cg.shared.global [%0], [%1], 16;" :: "r"(dst), "l"(src) : "memory")
#define CP_A16Z(dst, src, sz) asm volatile("cp.async.cg.shared.global [%0], [%1], 16, %2;" :: "r"(dst), "l"(src), "r"(sz) : "memory")
#define CP_COMMIT()           asm volatile("cp.async.commit_group;" ::: "memory")
#define CP_WAIT(n)            asm volatile("cp.async.wait_group %0;" :: "n"(n) : "memory")

#define LDSM_X4(r, addr) \
    asm volatile("ldmatrix.sync.aligned.m8n8.x4.shared.b16 {%0,%1,%2,%3}, [%4];" \
        : "=r"((r)[0]),"=r"((r)[1]),"=r"((r)[2]),"=r"((r)[3]) : "r"(addr))
#define LDSM_X4_T(r, addr) \
    asm volatile("ldmatrix.sync.aligned.m8n8.x4.trans.shared.b16 {%0,%1,%2,%3}, [%4];" \
        : "=r"((r)[0]),"=r"((r)[1]),"=r"((r)[2]),"=r"((r)[3]) : "r"(addr))

#define MMA_BF16(d, a, b) \
    asm volatile("mma.sync.aligned.m16n8k16.row.col.f32.bf16.bf16.f32 " \
        "{%0,%1,%2,%3}, {%4,%5,%6,%7}, {%8,%9}, {%0,%1,%2,%3};" \
        : "+f"((d)[0]),"+f"((d)[1]),"+f"((d)[2]),"+f"((d)[3]) \
        : "r"((a)[0]),"r"((a)[1]),"r"((a)[2]),"r"((a)[3]), "r"((b)[0]),"r"((b)[1]))

// ---------------------------------------------------------------- batched warp-MMA GEMM (pre-split bf16, 3 passes)
// C = A @ W. CTA tile 128x128, K-step 32, 8 warps. blockIdx.z selects operand set.
// SMEM stage: A_hi[128x80B] | A_lo | B_hi[32x256B xor-swz] | B_lo
#define G_STAGE 36864u
#define G_SMEM  (2*36864 + 1024)

struct GemmZ {
    const __nv_bfloat16 *Ahi, *Alo, *Bhi, *Blo;
    float* C;
    __nv_bfloat16 *Chi, *Clo;
    const float* bias;
    int act;            // 0 none, 1 tanh, 2 sigmoid
};
struct GemmBatch { GemmZ z[3]; };

__global__ __launch_bounds__(256, 2)
void gemm_mma(GemmBatch gb, int M, int N, int K, int split_out) {
    extern __shared__ char dsm[];
    uint32_t sb = (smem_u32(dsm) + 1023u) & ~1023u;
    GemmZ zz = gb.z[blockIdx.z];

    int tid = threadIdx.x;
    int wid = tid >> 5, lane = tid & 31;
    int wm = wid >> 2, wn = wid & 3;
    int m0 = blockIdx.y * 128;
    int n0 = blockIdx.x * 128;
    int nt = K >> 5;

    auto issue = [&](int it) {
        uint32_t base = sb + (uint32_t)(it & 1) * G_STAGE;
        int k0 = it << 5;
        #pragma unroll
        for (int s = 0; s < 2; ++s) {
            int ca = tid + s * 256;
            int row = ca >> 2, cc = ca & 3;
            size_t so = (size_t)(m0 + row) * K + k0 + cc * 8;
            uint32_t da = base + (uint32_t)(row * 80 + cc * 16);
            CP_A16(da, zz.Ahi + so);
            CP_A16(da + 10240u, zz.Alo + so);
        }
        #pragma unroll
        for (int s = 0; s < 2; ++s) {
            int cb = tid + s * 256;
            int kk = cb >> 4, j = cb & 15;
            int gn = n0 + j * 8;
            uint32_t sz = (gn < N) ? 16u : 0u;
            size_t so = (size_t)(k0 + kk) * N + ((gn < N) ? gn : 0);
            uint32_t db = base + 20480u + (uint32_t)(kk * 256 + ((j ^ (kk & 7)) * 16));
            CP_A16Z(db, zz.Bhi + so, sz);
            CP_A16Z(db + 8192u, zz.Blo + so, sz);
        }
        CP_COMMIT();
    };

    float acc[4][4][4];
    #pragma unroll
    for (int i = 0; i < 4; i++)
        #pragma unroll
        for (int j = 0; j < 4; j++)
            #pragma unroll
            for (int q = 0; q < 4; q++) acc[i][j][q] = 0.f;

    issue(0);
    for (int it = 0; it < nt; ++it) {
        if (it + 1 < nt) { issue(it + 1); CP_WAIT(1); }
        else             { CP_WAIT(0); }
        __syncthreads();
        uint32_t base = sb + (uint32_t)(it & 1) * G_STAGE;

        #pragma unroll
        for (int h = 0; h < 2; ++h) {
            uint32_t a_hi[16], b_hi[8], tmp[16];
            int lrow = lane & 15, lchk = lane >> 4;
            uint32_t ad[4];
            #pragma unroll
            for (int mf = 0; mf < 4; ++mf) {
                ad[mf] = base + (uint32_t)((wm * 64 + mf * 16 + lrow) * 80 + (h * 2 + lchk) * 16);
                LDSM_X4(&a_hi[mf * 4], ad[mf]);
            }
            int krow = h * 16 + (lane & 15);
            uint32_t bd[2];
            #pragma unroll
            for (int pr = 0; pr < 2; ++pr) {
                int nabs = wn * 32 + pr * 16 + (lane >> 4) * 8;
                int clog = nabs >> 3;
                bd[pr] = base + 20480u + (uint32_t)(krow * 256 + ((clog ^ (krow & 7)) * 16));
                LDSM_X4_T(&b_hi[pr * 4], bd[pr]);
            }
            // pass hh
            #pragma unroll
            for (int mf = 0; mf < 4; ++mf)
                #pragma unroll
                for (int nf = 0; nf < 4; ++nf)
                    MMA_BF16(acc[mf][nf], &a_hi[mf * 4], (&b_hi[(nf >> 1) * 4 + (nf & 1) * 2]));
            // a_lo -> tmp, pass lh
            #pragma unroll
            for (int mf = 0; mf < 4; ++mf) LDSM_X4(&tmp[mf * 4], ad[mf] + 10240u);
            #pragma unroll
            for (int mf = 0; mf < 4; ++mf)
                #pragma unroll
                for (int nf = 0; nf < 4; ++nf)
                    MMA_BF16(acc[mf][nf], &tmp[mf * 4], (&b_hi[(nf >> 1) * 4 + (nf & 1) * 2]));
            // b_lo -> reuse b_hi regs, pass hl
            #pragma unroll
            for (int pr = 0; pr < 2; ++pr) LDSM_X4_T(&b_hi[pr * 4], bd[pr] + 8192u);
            #pragma unroll
            for (int mf = 0; mf < 4; ++mf)
                #pragma unroll
                for (int nf = 0; nf < 4; ++nf)
                    MMA_BF16(acc[mf][nf], &a_hi[mf * 4], (&b_hi[(nf >> 1) * 4 + (nf & 1) * 2]));
        }
        __syncthreads();
    }

    // ---- epilogue
    int rbase = lane >> 2;
    int cbase = (lane & 3) * 2;
    #pragma unroll
    for (int mf = 0; mf < 4; ++mf) {
        #pragma unroll
        for (int nf = 0; nf < 4; ++nf) {
            int col = n0 + wn * 32 + nf * 8 + cbase;
            if (col >= N) continue;
            float b0 = 0.f, b1 = 0.f;
            if (zz.bias) { b0 = zz.bias[col]; b1 = zz.bias[col + 1]; }
            #pragma unroll
            for (int half = 0; half < 2; ++half) {
                int row = m0 + wm * 64 + mf * 16 + rbase + half * 8;
                float t0 = acc[mf][nf][half * 2 + 0] + b0;
                float t1 = acc[mf][nf][half * 2 + 1] + b1;
                if (zz.act == 1) { t0 = tanhf(t0); t1 = tanhf(t1); }
                else if (zz.act == 2) {
                    t0 = 1.f / (1.f + __expf(-t0));
                    t1 = 1.f / (1.f + __expf(-t1));
                }
                if (!split_out) {
                    *(float2*)(zz.C + (size_t)row * N + col) = make_float2(t0, t1);
                } else {
                    uint32_t hw, lw;
                    cvt_split2(t0, t1, hw, lw);
                    *(uint32_t*)(zz.Chi + (size_t)row * N + col) = hw;
                    *(uint32_t*)(zz.Clo + (size_t)row * N + col) = lw;
                }
            }
        }
    }
}

// ---------------------------------------------------------------- kernel: batched weight split (one launch for all 12)
struct ConvJob { const float* src; int off; int sz; };
struct ConvBatch { ConvJob j[12]; };
__global__ void conv_split_all(ConvBatch cb) {
    ConvJob jb = cb.j[blockIdx.y];
    int np = jb.sz >> 1;
    int p = blockIdx.x * blockDim.x + threadIdx.x;
    if (p >= np) return;
    float2 v = ((const float2*)jb.src)[p];
    uint32_t hw, lw;
    cvt_split2(v.x, v.y, hw, lw);
    ((uint32_t*)(g_wsplit + jb.off))[p] = hw;
    ((uint32_t*)(g_wsplit + jb.off + jb.sz))[p] = lw;
}

// ---------------------------------------------------------------- kernel: token-shift mixes -> bf16 hi/lo planes
__global__ void prep6_kernel(const float* __restrict__ x,
                             const float* __restrict__ mr, const float* __restrict__ mw,
                             const float* __restrict__ mk, const float* __restrict__ mv,
                             const float* __restrict__ ma, const float* __restrict__ mg) {
    int p = blockIdx.x * blockDim.x + threadIdx.x;
    if (p >= BTH / 2) return;
    int idx = p * 2;
    int ch = idx & (Hh - 1);
    int tok = idx >> 10;
    int t = tok & (Tt - 1);
    float x0 = x[idx], x1 = x[idx + 1];
    float d0 = ((t == 0) ? 0.f : x[idx - Hh]) - x0;
    float d1 = ((t == 0) ? 0.f : x[idx - Hh + 1]) - x1;

    float* dsts[6] = { g_xr, g_xw, g_xk, g_xv, g_xa, g_xg };
    const float* ms[6] = { mr, mw, mk, mv, ma, mg };
    #pragma unroll
    for (int i = 0; i < 6; ++i) {
        float v0 = x0 + d0 * ms[i][ch];
        float v1 = x1 + d1 * ms[i][ch + 1];
        uint32_t hw, lw;
        cvt_split2(v0, v1, hw, lw);
        __nv_bfloat16* base = (__nv_bfloat16*)dsts[i];
        ((uint32_t*)base)[p] = hw;
        ((uint32_t*)(base + BTH))[p] = lw;
    }
}

// ---------------------------------------------------------------- kernel: per-(token,head) prep (8 warps/block)
__global__ __launch_bounds__(256)
void prep_scan_kernel(const float* __restrict__ v_first,
                      const float* __restrict__ k_k,
                      const float* __restrict__ k_a) {
    int bh = blockIdx.x * 8 + (threadIdx.x >> 5);
    int lane = threadIdx.x & 31;
    int tok = bh >> 4;
    int h = bh & 15;
    int b = tok >> 11;
    int t = tok & (Tt - 1);
    int ofs = tok * Hh + h * 64;
    int hofs = (((b * NHh + h) * Tt) + t) * 64;
    int hd0 = h * 64 + lane, hd1 = hd0 + 32;

    float kv0 = g_k[ofs + lane],  kv1 = g_k[ofs + lane + 32];
    float av0 = g_al[ofs + lane], av1 = g_al[ofs + lane + 32];
    float kk0 = kv0 * k_k[hd0],   kk1 = kv1 * k_k[hd1];
    float ss = warp_sum(kk0 * kk0 + kk1 * kk1);
    float inv = 1.f / fmaxf(sqrtf(ss), 1e-12f);

    float r0 = g_r[ofs + lane],   r1 = g_r[ofs + lane + 32];
    float w0 = g_wl[ofs + lane],  w1 = g_wl[ofs + lane + 32];
    float vv0 = g_v0[ofs + lane], vv1 = g_v0[ofs + lane + 32];
    float vl0 = g_vl[ofs + lane], vl1 = g_vl[ofs + lane + 32];
    float vf0 = v_first[ofs + lane], vf1 = v_first[ofs + lane + 32];

    #pragma unroll
    for (int e = 0; e < 2; e++) {
        int d = lane + e * 32;
        float kv = e ? kv1 : kv0;
        float aa = e ? av1 : av0;
        float kkn = (e ? kk1 : kk0) * inv;
        g_aH[hofs + d] = -kkn;
        g_bH[hofs + d] = kkn * aa;
        g_kH[hofs + d] = kv * (1.f + (aa - 1.f) * k_a[h * 64 + d]);
        g_rH[hofs + d] = e ? r1 : r0;
        g_wHe[hofs + d] = __expf(DECAYC * (e ? w1 : w0));
        float v0v = e ? vv1 : vv0;
        g_vH[hofs + d] = v0v + (e ? vl1 : vl0) * ((e ? vf1 : vf0) - v0v);
    }
}

// ---------------------------------------------------------------- kernel: WKV7 scan, quarter-head blocks, cp.async ring
// 256 blocks (head, quarter): 16 v-rows x 64 k. 128 threads: r=tid>>3 (16 rows), c=tid&7 (8 k-chunks of 8).
__global__ __launch_bounds__(128)
void scan_kernel() {
    int head = blockIdx.x >> 2;
    int quarter = blockIdx.x & 3;
    size_t base = (size_t)head * Tt * 64;
    int tid = threadIdx.x;
    int v = quarter * 16 + (tid >> 3);
    int c = tid & 7;
    int co = c * 8;

    __shared__ __align__(16) float ring[8][384];

    const float* srcs[6] = { g_rH + base, g_wHe + base, g_kH + base,
                             g_vH + base, g_aH + base, g_bH + base };
    bool active = tid < 96;
    int arr = tid >> 4, cc = tid & 15;
    const float* src0 = srcs[active ? arr : 0] + cc * 4;
    uint32_t dofs = (uint32_t)(arr * 256 + cc * 16);

    auto issue = [&](int tt, int slot) {
        if (active) CP_A16(smem_u32(&ring[slot][0]) + dofs, src0 + (size_t)tt * 64);
        CP_COMMIT();
    };

    #pragma unroll
    for (int s = 0; s < 7; ++s) issue(s, s);

    float S[8];
    #pragma unroll
    for (int j = 0; j < 8; j++) S[j] = 0.f;

    float* outp = g_oH + base + v;

    for (int t = 0; t < Tt; ++t) {
        CP_WAIT(6);
        __syncthreads();
        // safe: any warp's reads of slot (t-1) happened before this barrier
        int tt = (t + 7 < Tt) ? t + 7 : Tt - 1;
        issue(tt, (t + 7) & 7);

        const float* cu = ring[t & 7];
        float rL[8], wL[8], kL[8], aL[8], bL[8];
        #pragma unroll
        for (int q = 0; q < 2; ++q) {
            *(float4*)(rL + q * 4) = *(const float4*)(cu + co + q * 4);
            *(float4*)(wL + q * 4) = *(const float4*)(cu + 64 + co + q * 4);
            *(float4*)(kL + q * 4) = *(const float4*)(cu + 128 + co + q * 4);
            *(float4*)(aL + q * 4) = *(const float4*)(cu + 256 + co + q * 4);
            *(float4*)(bL + q * 4) = *(const float4*)(cu + 320 + co + q * 4);
        }
        float vt = cu[192 + v];

        float sa = 0.f;
        #pragma unroll
        for (int j = 0; j < 8; j++) sa += S[j] * aL[j];
        sa += __shfl_xor_sync(0xffffffffu, sa, 1);
        sa += __shfl_xor_sync(0xffffffffu, sa, 2);
        sa += __shfl_xor_sync(0xffffffffu, sa, 4);

        float o = 0.f;
        #pragma unroll
        for (int j = 0; j < 8; j++) {
            float s = S[j] * wL[j] + sa * bL[j] + vt * kL[j];
            S[j] = s;
            o += s * rL[j];
        }
        o += __shfl_xor_sync(0xffffffffu, o, 1);
        o += __shfl_xor_sync(0xffffffffu, o, 2);
        o += __shfl_xor_sync(0xffffffffu, o, 4);
        if (c == 0) outp[(size_t)t * 64] = o;
    }
}

// ---------------------------------------------------------------- kernel: groupnorm + corr + gate -> y bf16 planes
__global__ __launch_bounds__(256)
void out_stage_kernel(const float* __restrict__ r_k,
                      const float* __restrict__ gn_w,
                      const float* __restrict__ gn_b) {
    int bh = blockIdx.x * 8 + (threadIdx.x >> 5);
    int lane = threadIdx.x & 31;
    int tok = bh >> 4;
    int h = bh & 15;
    int b = tok >> 11;
    int t = tok & (Tt - 1);
    int ofs = tok * Hh + h * 64;
    int hofs = (((b * NHh + h) * Tt) + t) * 64;
    int d0 = lane * 2, d1 = d0 + 1;

    float o0 = g_oH[hofs + d0], o1 = g_oH[hofs + d1];
    float r0 = g_rH[hofs + d0], r1 = g_rH[hofs + d1];
    float k0 = g_kH[hofs + d0], k1 = g_kH[hofs + d1];
    float v0 = g_vH[hofs + d0], v1 = g_vH[hofs + d1];

    float mu = warp_sum(o0 + o1) * (1.f / 64.f);
    float sq = warp_sum(o0 * o0 + o1 * o1) * (1.f / 64.f);
    float var = sq - mu * mu;
    float rstd = rsqrtf(var + GN_EPS);
    float dot = warp_sum(r0 * k0 * r_k[h * 64 + d0] + r1 * k1 * r_k[h * 64 + d1]);

    float gl0 = g_gl[ofs + d0], gl1 = g_gl[ofs + d1];
    float on0 = (o0 - mu) * rstd * gn_w[h * 64 + d0] + gn_b[h * 64 + d0];
    float on1 = (o1 - mu) * rstd * gn_w[h * 64 + d1] + gn_b[h * 64 + d1];
    float y0 = (on0 + dot * v0) * gl0;
    float y1 = (on1 + dot * v1) * gl1;

    uint32_t hw, lw;
    cvt_split2(y0, y1, hw, lw);
    __nv_bfloat16* ybase = (__nv_bfloat16*)g_y;
    ((uint32_t*)ybase)[(ofs + d0) >> 1] = hw;
    ((uint32_t*)(ybase + BTH))[(ofs + d0) >> 1] = lw;
}

// ---------------------------------------------------------------- launch
extern "C" void kernel_launch(void* const* d_in, const int* in_sizes, int n_in,
                              void* d_out, int out_size) {
    const float* x       = (const float*)d_in[0];
    const float* v_first = (const float*)d_in[1];
    const float* x_r = (const float*)d_in[2];
    const float* x_w = (const float*)d_in[3];
    const float* x_k = (const float*)d_in[4];
    const float* x_v = (const float*)d_in[5];
    const float* x_a = (const float*)d_in[6];
    const float* x_g = (const float*)d_in[7];
    const float* k_k = (const float*)d_in[8];
    const float* k_a = (const float*)d_in[9];
    const float* r_k = (const float*)d_in[10];
    const float* W_r = (const float*)d_in[11];
    const float* W_k = (const float*)d_in[12];
    const float* W_v = (const float*)d_in[13];
    const float* W_o = (const float*)d_in[14];
    const float* wA  = (const float*)d_in[15];
    const float* wB  = (const float*)d_in[16];
    const float* wb  = (const float*)d_in[17];
    const float* vA  = (const float*)d_in[18];
    const float* vB  = (const float*)d_in[19];
    const float* vb  = (const float*)d_in[20];
    const float* aA  = (const float*)d_in[21];
    const float* aB  = (const float*)d_in[22];
    const float* ab  = (const float*)d_in[23];
    const float* gA  = (const float*)d_in[24];
    const float* gB  = (const float*)d_in[25];
    const float* gn_w = (const float*)d_in[26];
    const float* gn_b = (const float*)d_in[27];
    float* out = (float*)d_out;

    float *p_xr, *p_xw, *p_xk, *p_xv, *p_xa, *p_xg;
    float *p_r, *p_k, *p_v0, *p_hw, *p_hv, *p_ha, *p_hg;
    float *p_wl, *p_vl, *p_al, *p_gl;
    __nv_bfloat16* p_ws;
    cudaGetSymbolAddress((void**)&p_xr, g_xr);
    cudaGetSymbolAddress((void**)&p_xw, g_xw);
    cudaGetSymbolAddress((void**)&p_xk, g_xk);
    cudaGetSymbolAddress((void**)&p_xv, g_xv);
    cudaGetSymbolAddress((void**)&p_xa, g_xa);
    cudaGetSymbolAddress((void**)&p_xg, g_xg);
    cudaGetSymbolAddress((void**)&p_r,  g_r);
    cudaGetSymbolAddress((void**)&p_k,  g_k);
    cudaGetSymbolAddress((void**)&p_v0, g_v0);
    cudaGetSymbolAddress((void**)&p_hw, g_hw);
    cudaGetSymbolAddress((void**)&p_hv, g_hv);
    cudaGetSymbolAddress((void**)&p_ha, g_ha);
    cudaGetSymbolAddress((void**)&p_hg, g_hg);
    cudaGetSymbolAddress((void**)&p_wl, g_wl);
    cudaGetSymbolAddress((void**)&p_vl, g_vl);
    cudaGetSymbolAddress((void**)&p_al, g_al);
    cudaGetSymbolAddress((void**)&p_gl, g_gl);
    cudaGetSymbolAddress((void**)&p_ws, g_wsplit);

    cudaFuncSetAttribute(gemm_mma, cudaFuncAttributeMaxDynamicSharedMemorySize, G_SMEM);

    // ---- weight splits: ONE launch for all 12 weights
    {
        ConvBatch cb = {{
            {W_r, OFF_WR, SZ_BIG}, {W_k, OFF_WK, SZ_BIG}, {W_v, OFF_WV, SZ_BIG}, {W_o, OFF_WO, SZ_BIG},
            {wA, OFF_wA, SZ_LORA}, {vA, OFF_vA, SZ_LORA}, {aA, OFF_aA, SZ_LORA}, {gA, OFF_gA, SZ_G},
            {wB, OFF_wB, SZ_LORA}, {vB, OFF_vB, SZ_LORA}, {aB, OFF_aB, SZ_LORA}, {gB, OFF_gB, SZ_G},
        }};
        conv_split_all<<<dim3((SZ_BIG / 2 + 255) / 256, 12), 256>>>(cb);
    }

    // ---- token-shift mixes (writes bf16 planes)
    prep6_kernel<<<(BTH / 2 + 255) / 256, 256>>>(x, x_r, x_w, x_k, x_v, x_a, x_g);

    auto planes = [&](float* f) {
        return (__nv_bfloat16*)f;
    };
    GemmZ Z0 = {};

    // ---- big3 batched: r, k, v0
    {
        GemmBatch gbm = {};
        __nv_bfloat16* a[3] = { planes(p_xr), planes(p_xk), planes(p_xv) };
        int woff[3] = { OFF_WR, OFF_WK, OFF_WV };
        float* cc[3] = { p_r, p_k, p_v0 };
        for (int i = 0; i < 3; ++i) {
            gbm.z[i] = Z0;
            gbm.z[i].Ahi = a[i]; gbm.z[i].Alo = a[i] + BTH;
            gbm.z[i].Bhi = p_ws + woff[i]; gbm.z[i].Blo = p_ws + woff[i] + SZ_BIG;
            gbm.z[i].C = cc[i];
        }
        gemm_mma<<<dim3(8, 64, 3), 256, G_SMEM>>>(gbm, BT, 1024, 1024, 0);
    }
    // ---- LoRA stage1 batched (N=64): hw(tanh), hv, ha  [split outputs]
    {
        GemmBatch gbm = {};
        __nv_bfloat16* a[3] = { planes(p_xw), planes(p_xv), planes(p_xa) };
        int woff[3] = { OFF_wA, OFF_vA, OFF_aA };
        float* cc[3] = { p_hw, p_hv, p_ha };
        int act[3] = { 1, 0, 0 };
        for (int i = 0; i < 3; ++i) {
            gbm.z[i] = Z0;
            gbm.z[i].Ahi = a[i]; gbm.z[i].Alo = a[i] + BTH;
            gbm.z[i].Bhi = p_ws + woff[i]; gbm.z[i].Blo = p_ws + woff[i] + SZ_LORA;
            gbm.z[i].Chi = planes(cc[i]); gbm.z[i].Clo = planes(cc[i]) + BT * 64;
            gbm.z[i].act = act[i];
        }
        gemm_mma<<<dim3(1, 64, 3), 256, G_SMEM>>>(gbm, BT, 64, 1024, 1);
    }
    // ---- gA stage1 (N=160, sigmoid, split out)
    {
        GemmBatch gbm = {};
        gbm.z[0] = Z0;
        gbm.z[0].Ahi = planes(p_xg); gbm.z[0].Alo = planes(p_xg) + BTH;
        gbm.z[0].Bhi = p_ws + OFF_gA; gbm.z[0].Blo = p_ws + OFF_gA + SZ_G;
        gbm.z[0].Chi = planes(p_hg); gbm.z[0].Clo = planes(p_hg) + BT * 160;
        gbm.z[0].act = 2;
        gemm_mma<<<dim3(2, 64, 1), 256, G_SMEM>>>(gbm, BT, 160, 1024, 1);
    }
    // ---- stage2 batched (K=64): wl, vl, al (sigmoid + bias)
    {
        GemmBatch gbm = {};
        float* a[3] = { p_hw, p_hv, p_ha };
        int woff[3] = { OFF_wB, OFF_vB, OFF_aB };
        float* cc[3] = { p_wl, p_vl, p_al };
        const float* bias[3] = { wb, vb, ab };
        for (int i = 0; i < 3; ++i) {
            gbm.z[i] = Z0;
            gbm.z[i].Ahi = planes(a[i]); gbm.z[i].Alo = planes(a[i]) + BT * 64;
            gbm.z[i].Bhi = p_ws + woff[i]; gbm.z[i].Blo = p_ws + woff[i] + SZ_LORA;
            gbm.z[i].C = cc[i]; gbm.z[i].bias = bias[i]; gbm.z[i].act = 2;
        }
        gemm_mma<<<dim3(8, 64, 3), 256, G_SMEM>>>(gbm, BT, 1024, 64, 0);
    }
    // ---- gB stage2 (K=160): gl
    {
        GemmBatch gbm = {};
        gbm.z[0] = Z0;
        gbm.z[0].Ahi = planes(p_hg); gbm.z[0].Alo = planes(p_hg) + BT * 160;
        gbm.z[0].Bhi = p_ws + OFF_gB; gbm.z[0].Blo = p_ws + OFF_gB + SZ_G;
        gbm.z[0].C = p_gl;
        gemm_mma<<<dim3(8, 64, 1), 256, G_SMEM>>>(gbm, BT, 1024, 160, 0);
    }

    // ---- head-layout prep (x-bufs dead -> reused)
    prep_scan_kernel<<<BT * NHh / 8, 256>>>(v_first, k_k, k_a);

    // ---- sequential scan (quarter-head blocks)
    scan_kernel<<<Bb * NHh * 4, 128>>>();

    // ---- groupnorm + corr + gate -> y bf16 planes (in g_vl, dead)
    out_stage_kernel<<<BT * NHh / 8, 256>>>(r_k, gn_w, gn_b);

    // ---- output projection
    {
        GemmBatch gbm = {};
        gbm.z[0] = Z0;
        gbm.z[0].Ahi = planes(p_vl); gbm.z[0].Alo = planes(p_vl) + BTH;
        gbm.z[0].Bhi = p_ws + OFF_WO; gbm.z[0].Blo = p_ws + OFF_WO + SZ_BIG;
        gbm.z[0].C = out;
        gemm_mma<<<dim3(8, 64, 1), 256, G_SMEM>>>(gbm, BT, 1024, 1024, 0);
    }

    (void)in_sizes; (void)n_in; (void)out_size;
}